// round 8
// baseline (speedup 1.0000x reference)
#include <cuda_runtime.h>
#include <cuda_bf16.h>
#include <math.h>
#include <stdint.h>

#define Bb   16
#define Ss   1024
#define Ee   256
#define Hh   256
#define FHh  512
#define Vv   8000
#define WSw  5
#define NTOK (Bb*Ss)     /* 16384 */
#define G4H  (4*Hh)      /* 1024  */

// ---------------- scratch (device globals; no dynamic allocation) ----------
__device__ float g_PVp[2][(size_t)Vv * G4H];            // permuted-col input projections
__device__ __nv_bfloat16 g_hA[2][2][2][(size_t)NTOK * Hh];  // [dir][pingpong][hi/lo] h bf16
__device__ float g_cst[2][(size_t)NTOK * Hh];           // [dir] c state
__device__ __nv_bfloat16 g_fcA[2][(size_t)NTOK * FHh];  // [hi/lo] leaky(h) concat, fc1 A
__device__ float g_fc1[(size_t)NTOK * FHh];
// pre-split bf16 hi/lo, col-permuted, pre-swizzled weight tiles (128 rows x 64 k = 16KB)
__device__ unsigned char g_Bsw[2][2][8][4][16384];      // Whh  [dir][hl][nblk][kc]
__device__ unsigned char g_BswIH[2][2][8][4][16384];    // Wih  [dir][hl][nblk][kc]
__device__ unsigned char g_fc1Bsw[2][4][8][16384];      // fc1_w [hl][nblk][kc]
__device__ float g_bsum[2][G4H];                        // permuted bih+bhh

__device__ __forceinline__ float sigmoidf_(float x) { return 1.0f / (1.0f + expf(-x)); }
__device__ __forceinline__ float leakyf_(float x)   { return x > 0.0f ? x : 0.01f * x; }
__device__ __forceinline__ uint32_t swz128(uint32_t off) { return off ^ ((off >> 3) & 0x70); }
__device__ __forceinline__ uint32_t smem_u32(const void* p) {
    uint32_t a;
    asm("{ .reg .u64 t; cvta.to.shared.u64 t, %1; cvt.u32.u64 %0, t; }" : "=r"(a) : "l"(p));
    return a;
}
__device__ __forceinline__ void ldsm4(uint32_t* r, uint32_t addr) {
    asm volatile("ldmatrix.sync.aligned.m8n8.x4.shared.b16 {%0,%1,%2,%3}, [%4];"
        : "=r"(r[0]), "=r"(r[1]), "=r"(r[2]), "=r"(r[3]) : "r"(addr));
}
__device__ __forceinline__ void mma_bf16(float* d, const uint32_t* a, const uint32_t* b) {
    asm volatile("mma.sync.aligned.m16n8k16.row.col.f32.bf16.bf16.f32 "
        "{%0,%1,%2,%3}, {%4,%5,%6,%7}, {%8,%9}, {%0,%1,%2,%3};"
        : "+f"(d[0]), "+f"(d[1]), "+f"(d[2]), "+f"(d[3])
        : "r"(a[0]), "r"(a[1]), "r"(a[2]), "r"(a[3]), "r"(b[0]), "r"(b[1]));
}
__device__ __forceinline__ uint32_t packbf(__nv_bfloat16 a, __nv_bfloat16 b) {
    unsigned short ua = *(unsigned short*)&a, ub = *(unsigned short*)&b;
    return (uint32_t)ua | ((uint32_t)ub << 16);
}
__device__ __forceinline__ void split8(const float* v, uint4* hi, uint4* lo) {
    __nv_bfloat16 h[8];
    uint32_t hw[4], lw[4];
#pragma unroll
    for (int j = 0; j < 8; j++) h[j] = __float2bfloat16(v[j]);
#pragma unroll
    for (int j = 0; j < 4; j++) {
        hw[j] = packbf(h[2 * j], h[2 * j + 1]);
        lw[j] = packbf(__float2bfloat16(v[2 * j]     - __bfloat162float(h[2 * j])),
                       __float2bfloat16(v[2 * j + 1] - __bfloat162float(h[2 * j + 1])));
    }
    *hi = make_uint4(hw[0], hw[1], hw[2], hw[3]);
    *lo = make_uint4(lw[0], lw[1], lw[2], lw[3]);
}

#define GM_SMEM (1024 + 65536 + 512)

// ---------------------------------------------------------------------------
// prep_all: blocks [0,256) Whh split (+bias), [256,512) Wih split,
//           [512,640) fc1_w split. Permutation p = unit*4+gate for Whh/Wih.
// ---------------------------------------------------------------------------
__global__ void __launch_bounds__(256) prep_all(const float* __restrict__ Whf, const float* __restrict__ Whb,
                                                const float* __restrict__ Wif, const float* __restrict__ Wib,
                                                const float* __restrict__ fc1w,
                                                const float* __restrict__ bihf, const float* __restrict__ bhhf,
                                                const float* __restrict__ bihb, const float* __restrict__ bhhb)
{
    const int blk = blockIdx.x;
    const int tid = threadIdx.x;
    if (blk < 512) {
        const int sect = blk >> 8;                       // 0 = Whh, 1 = Wih
        int idx = (blk & 255) * 256 + tid;               // 65536 per section
        int dir = idx >> 15;
        int r = idx & 32767;
        int n = r >> 5;
        int k8 = (r & 31) << 3;
        const float* W = sect ? (dir ? Wib : Wif) : (dir ? Whb : Whf);
        int p = ((n & 255) << 2) | (n >> 8);             // unit*4 + gate
        int nblk = p >> 7, prow = p & 127;
        float4 v0 = *(const float4*)(W + (size_t)n * Hh + k8);
        float4 v1 = *(const float4*)(W + (size_t)n * Hh + k8 + 4);
        float vals[8] = {v0.x, v0.y, v0.z, v0.w, v1.x, v1.y, v1.z, v1.w};
#pragma unroll
        for (int j = 0; j < 8; j++) {
            int k = k8 + j;
            int kc = k >> 6, kb = k & 63;
            uint32_t off = swz128((uint32_t)prow * 128u + (uint32_t)kb * 2u);
            __nv_bfloat16 hi = __float2bfloat16(vals[j]);
            __nv_bfloat16 lo = __float2bfloat16(vals[j] - __bfloat162float(hi));
            if (sect == 0) {
                *(__nv_bfloat16*)(&g_Bsw[dir][0][nblk][kc][off]) = hi;
                *(__nv_bfloat16*)(&g_Bsw[dir][1][nblk][kc][off]) = lo;
            } else {
                *(__nv_bfloat16*)(&g_BswIH[dir][0][nblk][kc][off]) = hi;
                *(__nv_bfloat16*)(&g_BswIH[dir][1][nblk][kc][off]) = lo;
            }
        }
        if (sect == 0 && k8 == 0) {
            const float* bi = dir ? bihb : bihf;
            const float* bh = dir ? bhhb : bhhf;
            g_bsum[dir][p] = bi[n] + bh[n];
        }
    } else {
        int idx = (blk - 512) * 256 + tid;               // 32768 threads
        int n = idx >> 6;                                // 0..511
        int k8 = (idx & 63) << 3;
        int nblk = n >> 7, prow = n & 127;
        float4 v0 = *(const float4*)(fc1w + (size_t)n * FHh + k8);
        float4 v1 = *(const float4*)(fc1w + (size_t)n * FHh + k8 + 4);
        float vals[8] = {v0.x, v0.y, v0.z, v0.w, v1.x, v1.y, v1.z, v1.w};
#pragma unroll
        for (int j = 0; j < 8; j++) {
            int k = k8 + j;
            int kc = k >> 6, kb = k & 63;
            uint32_t off = swz128((uint32_t)prow * 128u + (uint32_t)kb * 2u);
            __nv_bfloat16 hi = __float2bfloat16(vals[j]);
            __nv_bfloat16 lo = __float2bfloat16(vals[j] - __bfloat162float(hi));
            *(__nv_bfloat16*)(&g_fc1Bsw[0][nblk][kc][off]) = hi;
            *(__nv_bfloat16*)(&g_fc1Bsw[1][nblk][kc][off]) = lo;
        }
    }
}

// ---------------------------------------------------------------------------
// pv_mma: PVp[dir] = embed(row0=0) @ Wih^T, permuted cols, bf16 hi/lo 3-term.
// grid (8 nblk, 63 mtile, 2 dir), 256 thr.
// ---------------------------------------------------------------------------
__global__ void __launch_bounds__(256) pv_mma(const float* __restrict__ embed)
{
    extern __shared__ unsigned char smraw[];
    uint32_t sb0 = smem_u32(smraw);
    uint32_t sb = (sb0 + 1023u) & ~1023u;
    unsigned char* smb = smraw + (sb - sb0);

    const int dir = blockIdx.z;
    const int nblk = blockIdx.x;
    const int m0 = blockIdx.y << 7;
    const int tid = threadIdx.x;
    const int lane = tid & 31, wid = tid >> 5;
    const int wm = wid >> 2, wn = wid & 3;

    float acc[4][4][4];
#pragma unroll
    for (int a = 0; a < 4; a++)
#pragma unroll
        for (int b = 0; b < 4; b++)
#pragma unroll
            for (int c = 0; c < 4; c++) acc[a][b][c] = 0.f;

    const uint32_t aBaseH = sb, aBaseL = sb + 16384u, bBaseH = sb + 32768u, bBaseL = sb + 49152u;
    const int arow = (wm << 6) + (lane & 15);
    const int atop = (lane >> 4) << 4;
    const int brow = (wn << 5) + (lane & 7) + ((lane & 16) ? 8 : 0);
    const int btop = (lane & 8) ? 16 : 0;

    for (int kc = 0; kc < 4; kc++) {
        // A: embed rows fp32 -> bf16 hi/lo swizzled
#pragma unroll
        for (int i = 0; i < 4; i++) {
            int u = tid + (i << 8);
            int r = u >> 3, c8 = u & 7;
            int g = m0 + r;
            float vals[8];
            if (g == 0 || g >= Vv) {
#pragma unroll
                for (int j = 0; j < 8; j++) vals[j] = 0.f;
            } else {
                float4 v0 = *(const float4*)(embed + (size_t)g * Ee + (kc << 6) + (c8 << 3));
                float4 v1 = *(const float4*)(embed + (size_t)g * Ee + (kc << 6) + (c8 << 3) + 4);
                vals[0] = v0.x; vals[1] = v0.y; vals[2] = v0.z; vals[3] = v0.w;
                vals[4] = v1.x; vals[5] = v1.y; vals[6] = v1.z; vals[7] = v1.w;
            }
            uint4 hi, lo;
            split8(vals, &hi, &lo);
            uint32_t off = swz128((uint32_t)r * 128u + ((uint32_t)c8 << 4));
            *(uint4*)(smb + off) = hi;
            *(uint4*)(smb + 16384u + off) = lo;
        }
        // B: pre-swizzled copy
#pragma unroll
        for (int hl = 0; hl < 2; hl++) {
            const uint4* src = (const uint4*)&g_BswIH[dir][hl][nblk][kc][0];
            uint4* dst = (uint4*)(smb + 32768 + hl * 16384);
#pragma unroll
            for (int i = 0; i < 4; i++) dst[tid + (i << 8)] = src[tid + (i << 8)];
        }
        __syncthreads();

#pragma unroll
        for (int ks = 0; ks < 4; ks++) {
            const uint32_t kbyte = (uint32_t)ks << 5;
            uint32_t ah[4][4], al[4][4], bh[8], bl[8];
#pragma unroll
            for (int mi = 0; mi < 4; mi++) {
                uint32_t off = swz128((uint32_t)(arow + mi * 16) * 128u + kbyte + (uint32_t)atop);
                ldsm4(ah[mi], aBaseH + off);
                ldsm4(al[mi], aBaseL + off);
            }
#pragma unroll
            for (int bi = 0; bi < 2; bi++) {
                uint32_t off = swz128((uint32_t)(brow + bi * 16) * 128u + kbyte + (uint32_t)btop);
                ldsm4(bh + bi * 4, bBaseH + off);
                ldsm4(bl + bi * 4, bBaseL + off);
            }
#pragma unroll
            for (int mi = 0; mi < 4; mi++)
#pragma unroll
                for (int ni = 0; ni < 4; ni++) mma_bf16(acc[mi][ni], ah[mi], bh + ni * 2);
#pragma unroll
            for (int mi = 0; mi < 4; mi++)
#pragma unroll
                for (int ni = 0; ni < 4; ni++) mma_bf16(acc[mi][ni], ah[mi], bl + ni * 2);
#pragma unroll
            for (int mi = 0; mi < 4; mi++)
#pragma unroll
                for (int ni = 0; ni < 4; ni++) mma_bf16(acc[mi][ni], al[mi], bh + ni * 2);
        }
        __syncthreads();
    }

    // epilogue: direct register store (rows < Vv)
    float* out = g_PVp[dir];
#pragma unroll
    for (int mi = 0; mi < 4; mi++) {
        int r0 = m0 + (wm << 6) + mi * 16 + (lane >> 2);
#pragma unroll
        for (int ni = 0; ni < 4; ni++) {
            int c0 = (nblk << 7) + (wn << 5) + ni * 8 + ((lane & 3) << 1);
            if (r0 < Vv)
                *(float2*)(out + (size_t)r0 * G4H + c0) = make_float2(acc[mi][ni][0], acc[mi][ni][1]);
            if (r0 + 8 < Vv)
                *(float2*)(out + (size_t)(r0 + 8) * G4H + c0) = make_float2(acc[mi][ni][2], acc[mi][ni][3]);
        }
    }
}

// ---------------------------------------------------------------------------
// zero h (buf0 hi/lo, both dirs) and c (both dirs)
// ---------------------------------------------------------------------------
__global__ void __launch_bounds__(256) zero_state()
{
    const int i = blockIdx.x * 256 + threadIdx.x;
    const uint4 z = make_uint4(0u, 0u, 0u, 0u);
    if (i < 2097152) {
        int slice = i >> 19;
        int dir = slice >> 1, hl = slice & 1;
        ((uint4*)g_hA[dir][0][hl])[i & 524287] = z;
    } else {
        int j = i - 2097152;
        int dir = j >> 20;
        ((uint4*)g_cst[dir])[j & 1048575] = z;
    }
}

// ---------------------------------------------------------------------------
// gates_mma: one LSTM step, both dirs (term-outermost mma for ILP).
// ---------------------------------------------------------------------------
__global__ void __launch_bounds__(256) gates_mma(const int* __restrict__ x, int step)
{
    extern __shared__ unsigned char smraw[];
    uint32_t sb0 = smem_u32(smraw);
    uint32_t sb = (sb0 + 1023u) & ~1023u;
    unsigned char* smb = smraw + (sb - sb0);

    const int dir = blockIdx.z;
    const int nblk = blockIdx.x;
    const int m0 = blockIdx.y << 7;
    const int tid = threadIdx.x;
    const int lane = tid & 31, wid = tid >> 5;
    const int wm = wid >> 2, wn = wid & 3;
    const int buf = step & 1, nbuf = buf ^ 1;

    float* biasf = (float*)(smb + 65536);
    if (tid < 32)
        *(float4*)(biasf + (tid << 2)) = *(const float4*)(g_bsum[dir] + (nblk << 7) + (tid << 2));

    float acc[4][4][4];
#pragma unroll
    for (int a = 0; a < 4; a++)
#pragma unroll
        for (int b = 0; b < 4; b++)
#pragma unroll
            for (int c = 0; c < 4; c++) acc[a][b][c] = 0.f;

    const uint32_t aBaseH = sb, aBaseL = sb + 16384u, bBaseH = sb + 32768u, bBaseL = sb + 49152u;
    const int arow = (wm << 6) + (lane & 15);
    const int atop = (lane >> 4) << 4;
    const int brow = (wn << 5) + (lane & 7) + ((lane & 16) ? 8 : 0);
    const int btop = (lane & 8) ? 16 : 0;

    for (int kc = 0; kc < 4; kc++) {
#pragma unroll
        for (int hl = 0; hl < 2; hl++) {
            const uint4* src = (const uint4*)g_hA[dir][buf][hl];
            unsigned char* dst = smb + hl * 16384;
#pragma unroll
            for (int i = 0; i < 4; i++) {
                int u = tid + (i << 8);
                int r = u >> 3, c16 = u & 7;
                uint4 v = src[(size_t)(m0 + r) * 32 + (kc << 3) + c16];
                *(uint4*)(dst + swz128((uint32_t)r * 128u + ((uint32_t)c16 << 4))) = v;
            }
        }
#pragma unroll
        for (int hl = 0; hl < 2; hl++) {
            const uint4* src = (const uint4*)&g_Bsw[dir][hl][nblk][kc][0];
            uint4* dst = (uint4*)(smb + 32768 + hl * 16384);
#pragma unroll
            for (int i = 0; i < 4; i++) dst[tid + (i << 8)] = src[tid + (i << 8)];
        }
        __syncthreads();

#pragma unroll
        for (int ks = 0; ks < 4; ks++) {
            const uint32_t kbyte = (uint32_t)ks << 5;
            uint32_t ah[4][4], al[4][4], bh[8], bl[8];
#pragma unroll
            for (int mi = 0; mi < 4; mi++) {
                uint32_t off = swz128((uint32_t)(arow + mi * 16) * 128u + kbyte + (uint32_t)atop);
                ldsm4(ah[mi], aBaseH + off);
                ldsm4(al[mi], aBaseL + off);
            }
#pragma unroll
            for (int bi = 0; bi < 2; bi++) {
                uint32_t off = swz128((uint32_t)(brow + bi * 16) * 128u + kbyte + (uint32_t)btop);
                ldsm4(bh + bi * 4, bBaseH + off);
                ldsm4(bl + bi * 4, bBaseL + off);
            }
#pragma unroll
            for (int mi = 0; mi < 4; mi++)
#pragma unroll
                for (int ni = 0; ni < 4; ni++) mma_bf16(acc[mi][ni], ah[mi], bh + ni * 2);
#pragma unroll
            for (int mi = 0; mi < 4; mi++)
#pragma unroll
                for (int ni = 0; ni < 4; ni++) mma_bf16(acc[mi][ni], ah[mi], bl + ni * 2);
#pragma unroll
            for (int mi = 0; mi < 4; mi++)
#pragma unroll
                for (int ni = 0; ni < 4; ni++) mma_bf16(acc[mi][ni], al[mi], bh + ni * 2);
        }
        __syncthreads();
    }

    // stage accumulators into smem (union over operand tiles)
    float* Acc = (float*)smb;
#pragma unroll
    for (int mi = 0; mi < 4; mi++)
#pragma unroll
        for (int ni = 0; ni < 4; ni++) {
            int r0 = (wm << 6) + mi * 16 + (lane >> 2);
            int c0 = (wn << 5) + ni * 8 + ((lane & 3) << 1);
            *(float2*)(Acc + r0 * 128 + c0) = make_float2(acc[mi][ni][0], acc[mi][ni][1]);
            *(float2*)(Acc + (r0 + 8) * 128 + c0) = make_float2(acc[mi][ni][2], acc[mi][ni][3]);
        }
    __syncthreads();

    // fused epilogue: 2 threads per row, 16 units each
    const int row_l = tid >> 1;
    const int half = tid & 1;
    const int row = m0 + row_l;
    const int t = row & (Ss - 1), bidx = row >> 10;
    const int tp = dir ? (t + WSw - step) : (t - WSw + step);
    const bool valid = ((unsigned)tp < (unsigned)Ss);
    const int tok = valid ? x[(bidx << 10) + tp] : 0;
    const bool finalstep = (step == WSw);

    const float4* accu = (const float4*)(Acc + row_l * 128 + (half << 6));
    const float4* bsu  = (const float4*)(biasf + (half << 6));
    const float4* pvu  = (const float4*)(g_PVp[dir] + (size_t)tok * G4H + (nblk << 7) + (half << 6));
    float4* cp = (float4*)(g_cst[dir] + (size_t)row * Hh + (nblk << 5) + (half << 4));
    const int colbase = (nblk << 5) + (half << 4);
    __nv_bfloat16* hip = g_hA[dir][nbuf][0] + (size_t)row * Hh + colbase;
    __nv_bfloat16* lop = g_hA[dir][nbuf][1] + (size_t)row * Hh + colbase;
    __nv_bfloat16* fHp = g_fcA[0] + (size_t)row * FHh + dir * Hh + colbase;
    __nv_bfloat16* fLp = g_fcA[1] + (size_t)row * FHh + dir * Hh + colbase;

    uint32_t hwH[8], hwL[8];
    uint32_t fwH[8], fwL[8];
#pragma unroll
    for (int g4 = 0; g4 < 4; g4++) {
        float4 cv = cp[g4];
        float cin[4] = {cv.x, cv.y, cv.z, cv.w};
        float ho[4];
#pragma unroll
        for (int j = 0; j < 4; j++) {
            int u = g4 * 4 + j;
            float4 gq = accu[u];
            float4 bq = bsu[u];
            float pi = gq.x + bq.x, pf = gq.y + bq.y, pg = gq.z + bq.z, po = gq.w + bq.w;
            if (valid) {
                float4 pq = pvu[u];
                pi += pq.x; pf += pq.y; pg += pq.z; po += pq.w;
            }
            float iv = sigmoidf_(pi), fv = sigmoidf_(pf), gv = tanhf(pg), ov = sigmoidf_(po);
            float cn = fv * cin[j] + iv * gv;
            cin[j] = cn;
            ho[j] = ov * tanhf(cn);
        }
        cp[g4] = make_float4(cin[0], cin[1], cin[2], cin[3]);
        __nv_bfloat16 h0 = __float2bfloat16(ho[0]), h1 = __float2bfloat16(ho[1]);
        __nv_bfloat16 h2 = __float2bfloat16(ho[2]), h3 = __float2bfloat16(ho[3]);
        hwH[g4 * 2 + 0] = packbf(h0, h1);
        hwH[g4 * 2 + 1] = packbf(h2, h3);
        hwL[g4 * 2 + 0] = packbf(__float2bfloat16(ho[0] - __bfloat162float(h0)),
                                 __float2bfloat16(ho[1] - __bfloat162float(h1)));
        hwL[g4 * 2 + 1] = packbf(__float2bfloat16(ho[2] - __bfloat162float(h2)),
                                 __float2bfloat16(ho[3] - __bfloat162float(h3)));
        if (finalstep) {
            float lk[4];
#pragma unroll
            for (int j = 0; j < 4; j++) lk[j] = leakyf_(ho[j]);
            __nv_bfloat16 f0 = __float2bfloat16(lk[0]), f1 = __float2bfloat16(lk[1]);
            __nv_bfloat16 f2 = __float2bfloat16(lk[2]), f3 = __float2bfloat16(lk[3]);
            fwH[g4 * 2 + 0] = packbf(f0, f1);
            fwH[g4 * 2 + 1] = packbf(f2, f3);
            fwL[g4 * 2 + 0] = packbf(__float2bfloat16(lk[0] - __bfloat162float(f0)),
                                     __float2bfloat16(lk[1] - __bfloat162float(f1)));
            fwL[g4 * 2 + 1] = packbf(__float2bfloat16(lk[2] - __bfloat162float(f2)),
                                     __float2bfloat16(lk[3] - __bfloat162float(f3)));
        }
    }
    *(uint4*)hip       = make_uint4(hwH[0], hwH[1], hwH[2], hwH[3]);
    *(uint4*)(hip + 8) = make_uint4(hwH[4], hwH[5], hwH[6], hwH[7]);
    *(uint4*)lop       = make_uint4(hwL[0], hwL[1], hwL[2], hwL[3]);
    *(uint4*)(lop + 8) = make_uint4(hwL[4], hwL[5], hwL[6], hwL[7]);
    if (finalstep) {
        *(uint4*)fHp       = make_uint4(fwH[0], fwH[1], fwH[2], fwH[3]);
        *(uint4*)(fHp + 8) = make_uint4(fwH[4], fwH[5], fwH[6], fwH[7]);
        *(uint4*)fLp       = make_uint4(fwL[0], fwL[1], fwL[2], fwL[3]);
        *(uint4*)(fLp + 8) = make_uint4(fwL[4], fwL[5], fwL[6], fwL[7]);
    }
}

// ---------------------------------------------------------------------------
// fc1_mma: g_fc1 = leaky( fcA @ fc1_w^T + fc1_b ), bf16 hi/lo 3-term.
// grid (4 nblk, 128 mtile), 256 thr. K=512 in 8 chunks.
// ---------------------------------------------------------------------------
__global__ void __launch_bounds__(256) fc1_mma(const float* __restrict__ fc1_b)
{
    extern __shared__ unsigned char smraw[];
    uint32_t sb0 = smem_u32(smraw);
    uint32_t sb = (sb0 + 1023u) & ~1023u;
    unsigned char* smb = smraw + (sb - sb0);

    const int nblk = blockIdx.x;
    const int m0 = blockIdx.y << 7;
    const int tid = threadIdx.x;
    const int lane = tid & 31, wid = tid >> 5;
    const int wm = wid >> 2, wn = wid & 3;

    float* biasf = (float*)(smb + 65536);
    if (tid < 32)
        *(float4*)(biasf + (tid << 2)) = *(const float4*)(fc1_b + (nblk << 7) + (tid << 2));

    float acc[4][4][4];
#pragma unroll
    for (int a = 0; a < 4; a++)
#pragma unroll
        for (int b = 0; b < 4; b++)
#pragma unroll
            for (int c = 0; c < 4; c++) acc[a][b][c] = 0.f;

    const uint32_t aBaseH = sb, aBaseL = sb + 16384u, bBaseH = sb + 32768u, bBaseL = sb + 49152u;
    const int arow = (wm << 6) + (lane & 15);
    const int atop = (lane >> 4) << 4;
    const int brow = (wn << 5) + (lane & 7) + ((lane & 16) ? 8 : 0);
    const int btop = (lane & 8) ? 16 : 0;

    for (int kc = 0; kc < 8; kc++) {
#pragma unroll
        for (int hl = 0; hl < 2; hl++) {
            const uint4* src = (const uint4*)g_fcA[hl];
            unsigned char* dst = smb + hl * 16384;
#pragma unroll
            for (int i = 0; i < 4; i++) {
                int u = tid + (i << 8);
                int r = u >> 3, c16 = u & 7;
                uint4 v = src[(size_t)(m0 + r) * 64 + (kc << 3) + c16];
                *(uint4*)(dst + swz128((uint32_t)r * 128u + ((uint32_t)c16 << 4))) = v;
            }
        }
#pragma unroll
        for (int hl = 0; hl < 2; hl++) {
            const uint4* src = (const uint4*)&g_fc1Bsw[hl][nblk][kc][0];
            uint4* dst = (uint4*)(smb + 32768 + hl * 16384);
#pragma unroll
            for (int i = 0; i < 4; i++) dst[tid + (i << 8)] = src[tid + (i << 8)];
        }
        __syncthreads();

#pragma unroll
        for (int ks = 0; ks < 4; ks++) {
            const uint32_t kbyte = (uint32_t)ks << 5;
            uint32_t ah[4][4], al[4][4], bh[8], bl[8];
#pragma unroll
            for (int mi = 0; mi < 4; mi++) {
                uint32_t off = swz128((uint32_t)(arow + mi * 16) * 128u + kbyte + (uint32_t)atop);
                ldsm4(ah[mi], aBaseH + off);
                ldsm4(al[mi], aBaseL + off);
            }
#pragma unroll
            for (int bi = 0; bi < 2; bi++) {
                uint32_t off = swz128((uint32_t)(brow + bi * 16) * 128u + kbyte + (uint32_t)btop);
                ldsm4(bh + bi * 4, bBaseH + off);
                ldsm4(bl + bi * 4, bBaseL + off);
            }
#pragma unroll
            for (int mi = 0; mi < 4; mi++)
#pragma unroll
                for (int ni = 0; ni < 4; ni++) mma_bf16(acc[mi][ni], ah[mi], bh + ni * 2);
#pragma unroll
            for (int mi = 0; mi < 4; mi++)
#pragma unroll
                for (int ni = 0; ni < 4; ni++) mma_bf16(acc[mi][ni], ah[mi], bl + ni * 2);
#pragma unroll
            for (int mi = 0; mi < 4; mi++)
#pragma unroll
                for (int ni = 0; ni < 4; ni++) mma_bf16(acc[mi][ni], al[mi], bh + ni * 2);
        }
        __syncthreads();
    }

    // epilogue: bias + leaky, direct register store
#pragma unroll
    for (int mi = 0; mi < 4; mi++) {
        int r0 = m0 + (wm << 6) + mi * 16 + (lane >> 2);
#pragma unroll
        for (int ni = 0; ni < 4; ni++) {
            int cl = (wn << 5) + ni * 8 + ((lane & 3) << 1);
            int c0 = (nblk << 7) + cl;
            float b0 = biasf[cl], b1 = biasf[cl + 1];
            *(float2*)(g_fc1 + (size_t)r0 * FHh + c0) =
                make_float2(leakyf_(acc[mi][ni][0] + b0), leakyf_(acc[mi][ni][1] + b1));
            *(float2*)(g_fc1 + (size_t)(r0 + 8) * FHh + c0) =
                make_float2(leakyf_(acc[mi][ni][2] + b0), leakyf_(acc[mi][ni][3] + b1));
        }
    }
}

// ---------------------------------------------------------------------------
// fc2: out[n] = sigmoid( g_fc1[n] . fc2_w + fc2_b )
// ---------------------------------------------------------------------------
__global__ void __launch_bounds__(128) fc2_kernel(const float* __restrict__ w,
                                                  const float* __restrict__ b,
                                                  float* __restrict__ out)
{
    const int n = blockIdx.x;
    const int t = threadIdx.x;
    const float4 a = ((const float4*)(g_fc1 + (size_t)n * FHh))[t];
    const float4 wv = ((const float4*)w)[t];
    float s = a.x * wv.x + a.y * wv.y + a.z * wv.z + a.w * wv.w;
#pragma unroll
    for (int o = 16; o > 0; o >>= 1) s += __shfl_xor_sync(0xffffffffu, s, o);
    __shared__ float ws[4];
    if ((t & 31) == 0) ws[t >> 5] = s;
    __syncthreads();
    if (t == 0) {
        const float tot = ws[0] + ws[1] + ws[2] + ws[3];
        out[n] = 1.0f / (1.0f + expf(-(tot + b[0])));
    }
}

// ---------------------------------------------------------------------------
extern "C" void kernel_launch(void* const* d_in, const int* in_sizes, int n_in,
                              void* d_out, int out_size)
{
    const int*   x      = (const int*)  d_in[0];
    const float* embed  = (const float*)d_in[1];
    const float* Wih_f  = (const float*)d_in[2];
    const float* Whh_f  = (const float*)d_in[3];
    const float* bih_f  = (const float*)d_in[4];
    const float* bhh_f  = (const float*)d_in[5];
    const float* Wih_b  = (const float*)d_in[6];
    const float* Whh_b  = (const float*)d_in[7];
    const float* bih_b  = (const float*)d_in[8];
    const float* bhh_b  = (const float*)d_in[9];
    const float* fc1_w  = (const float*)d_in[10];
    const float* fc1_b  = (const float*)d_in[11];
    const float* fc2_w  = (const float*)d_in[12];
    const float* fc2_b  = (const float*)d_in[13];
    float* out = (float*)d_out;

    cudaFuncSetAttribute(gates_mma, cudaFuncAttributeMaxDynamicSharedMemorySize, GM_SMEM);
    cudaFuncSetAttribute(pv_mma,    cudaFuncAttributeMaxDynamicSharedMemorySize, GM_SMEM);
    cudaFuncSetAttribute(fc1_mma,   cudaFuncAttributeMaxDynamicSharedMemorySize, GM_SMEM);

    prep_all<<<640, 256>>>(Whh_f, Whh_b, Wih_f, Wih_b, fc1_w,
                           bih_f, bhh_f, bih_b, bhh_b);
    pv_mma<<<dim3(8, 63, 2), 256, GM_SMEM>>>(embed);
    zero_state<<<16384, 256>>>();

    for (int k = 0; k <= WSw; k++) {
        gates_mma<<<dim3(8, NTOK / 128, 2), 256, GM_SMEM>>>(x, k);
    }

    fc1_mma<<<dim3(4, 128), 256, GM_SMEM>>>(fc1_b);
    fc2_kernel<<<NTOK, 128>>>(fc2_w, fc2_b, out);
}

// round 9
// speedup vs baseline: 1.0744x; 1.0744x over previous
#include <cuda_runtime.h>
#include <cuda_bf16.h>
#include <math.h>
#include <stdint.h>

#define Bb   16
#define Ss   1024
#define Ee   256
#define Hh   256
#define FHh  512
#define Vv   8000
#define WSw  5
#define NTOK (Bb*Ss)     /* 16384 */
#define G4H  (4*Hh)      /* 1024  */

// ---------------- scratch (device globals; no dynamic allocation) ----------
__device__ float g_PVp[2][(size_t)Vv * G4H];            // permuted-col input projections
__device__ __nv_bfloat16 g_hA[2][2][2][(size_t)NTOK * Hh];  // [dir][pingpong][hi/lo] h bf16
__device__ float g_cst[2][(size_t)NTOK * Hh];           // [dir] c state
__device__ __nv_bfloat16 g_fcA[2][(size_t)NTOK * FHh];  // [hi/lo] leaky(h) concat, fc1 A
__device__ float g_fc1[(size_t)NTOK * FHh];
// pre-split bf16 hi/lo, col-permuted, pre-swizzled weight tiles (128 rows x 64 k = 16KB)
__device__ unsigned char g_Bsw[2][2][8][4][16384];      // Whh  [dir][hl][nblk][kc]
__device__ unsigned char g_BswIH[2][2][8][4][16384];    // Wih  [dir][hl][nblk][kc]
__device__ unsigned char g_fc1Bsw[2][4][8][16384];      // fc1_w [hl][nblk][kc]
__device__ float g_bsum[2][G4H];                        // permuted bih+bhh

__device__ __forceinline__ float sigmoidf_(float x) { return 1.0f / (1.0f + expf(-x)); }
__device__ __forceinline__ float leakyf_(float x)   { return x > 0.0f ? x : 0.01f * x; }
__device__ __forceinline__ uint32_t swz128(uint32_t off) { return off ^ ((off >> 3) & 0x70); }
__device__ __forceinline__ uint32_t smem_u32(const void* p) {
    uint32_t a;
    asm("{ .reg .u64 t; cvta.to.shared.u64 t, %1; cvt.u32.u64 %0, t; }" : "=r"(a) : "l"(p));
    return a;
}
__device__ __forceinline__ void ldsm4(uint32_t* r, uint32_t addr) {
    asm volatile("ldmatrix.sync.aligned.m8n8.x4.shared.b16 {%0,%1,%2,%3}, [%4];"
        : "=r"(r[0]), "=r"(r[1]), "=r"(r[2]), "=r"(r[3]) : "r"(addr));
}
__device__ __forceinline__ void mma_bf16(float* d, const uint32_t* a, const uint32_t* b) {
    asm volatile("mma.sync.aligned.m16n8k16.row.col.f32.bf16.bf16.f32 "
        "{%0,%1,%2,%3}, {%4,%5,%6,%7}, {%8,%9}, {%0,%1,%2,%3};"
        : "+f"(d[0]), "+f"(d[1]), "+f"(d[2]), "+f"(d[3])
        : "r"(a[0]), "r"(a[1]), "r"(a[2]), "r"(a[3]), "r"(b[0]), "r"(b[1]));
}
__device__ __forceinline__ void cpasync16(uint32_t dst, const void* src) {
    asm volatile("cp.async.cg.shared.global [%0], [%1], 16;" :: "r"(dst), "l"(src));
}
#define CPASYNC_COMMIT() asm volatile("cp.async.commit_group;" ::: "memory")
#define CPASYNC_WAIT_ALL() asm volatile("cp.async.wait_group 0;" ::: "memory")

__device__ __forceinline__ uint32_t packbf(__nv_bfloat16 a, __nv_bfloat16 b) {
    unsigned short ua = *(unsigned short*)&a, ub = *(unsigned short*)&b;
    return (uint32_t)ua | ((uint32_t)ub << 16);
}
__device__ __forceinline__ void split8(const float* v, uint4* hi, uint4* lo) {
    __nv_bfloat16 h[8];
    uint32_t hw[4], lw[4];
#pragma unroll
    for (int j = 0; j < 8; j++) h[j] = __float2bfloat16(v[j]);
#pragma unroll
    for (int j = 0; j < 4; j++) {
        hw[j] = packbf(h[2 * j], h[2 * j + 1]);
        lw[j] = packbf(__float2bfloat16(v[2 * j]     - __bfloat162float(h[2 * j])),
                       __float2bfloat16(v[2 * j + 1] - __bfloat162float(h[2 * j + 1])));
    }
    *hi = make_uint4(hw[0], hw[1], hw[2], hw[3]);
    *lo = make_uint4(lw[0], lw[1], lw[2], lw[3]);
}

#define PV_SMEM   (1024 + 65536 + 512)
#define PIPE_SMEM (1024 + 131072 + 512)   /* 2 x 64KB stages + bias */

// ---------------------------------------------------------------------------
// prep_all: blocks [0,256) Whh split (+bias), [256,512) Wih split,
//           [512,640) fc1_w split. Permutation p = unit*4+gate for Whh/Wih.
// ---------------------------------------------------------------------------
__global__ void __launch_bounds__(256) prep_all(const float* __restrict__ Whf, const float* __restrict__ Whb,
                                                const float* __restrict__ Wif, const float* __restrict__ Wib,
                                                const float* __restrict__ fc1w,
                                                const float* __restrict__ bihf, const float* __restrict__ bhhf,
                                                const float* __restrict__ bihb, const float* __restrict__ bhhb)
{
    const int blk = blockIdx.x;
    const int tid = threadIdx.x;
    if (blk < 512) {
        const int sect = blk >> 8;                       // 0 = Whh, 1 = Wih
        int idx = (blk & 255) * 256 + tid;               // 65536 per section
        int dir = idx >> 15;
        int r = idx & 32767;
        int n = r >> 5;
        int k8 = (r & 31) << 3;
        const float* W = sect ? (dir ? Wib : Wif) : (dir ? Whb : Whf);
        int p = ((n & 255) << 2) | (n >> 8);             // unit*4 + gate
        int nblk = p >> 7, prow = p & 127;
        float4 v0 = *(const float4*)(W + (size_t)n * Hh + k8);
        float4 v1 = *(const float4*)(W + (size_t)n * Hh + k8 + 4);
        float vals[8] = {v0.x, v0.y, v0.z, v0.w, v1.x, v1.y, v1.z, v1.w};
#pragma unroll
        for (int j = 0; j < 8; j++) {
            int k = k8 + j;
            int kc = k >> 6, kb = k & 63;
            uint32_t off = swz128((uint32_t)prow * 128u + (uint32_t)kb * 2u);
            __nv_bfloat16 hi = __float2bfloat16(vals[j]);
            __nv_bfloat16 lo = __float2bfloat16(vals[j] - __bfloat162float(hi));
            if (sect == 0) {
                *(__nv_bfloat16*)(&g_Bsw[dir][0][nblk][kc][off]) = hi;
                *(__nv_bfloat16*)(&g_Bsw[dir][1][nblk][kc][off]) = lo;
            } else {
                *(__nv_bfloat16*)(&g_BswIH[dir][0][nblk][kc][off]) = hi;
                *(__nv_bfloat16*)(&g_BswIH[dir][1][nblk][kc][off]) = lo;
            }
        }
        if (sect == 0 && k8 == 0) {
            const float* bi = dir ? bihb : bihf;
            const float* bh = dir ? bhhb : bhhf;
            g_bsum[dir][p] = bi[n] + bh[n];
        }
    } else {
        int idx = (blk - 512) * 256 + tid;               // 32768 threads
        int n = idx >> 6;                                // 0..511
        int k8 = (idx & 63) << 3;
        int nblk = n >> 7, prow = n & 127;
        float4 v0 = *(const float4*)(fc1w + (size_t)n * FHh + k8);
        float4 v1 = *(const float4*)(fc1w + (size_t)n * FHh + k8 + 4);
        float vals[8] = {v0.x, v0.y, v0.z, v0.w, v1.x, v1.y, v1.z, v1.w};
#pragma unroll
        for (int j = 0; j < 8; j++) {
            int k = k8 + j;
            int kc = k >> 6, kb = k & 63;
            uint32_t off = swz128((uint32_t)prow * 128u + (uint32_t)kb * 2u);
            __nv_bfloat16 hi = __float2bfloat16(vals[j]);
            __nv_bfloat16 lo = __float2bfloat16(vals[j] - __bfloat162float(hi));
            *(__nv_bfloat16*)(&g_fc1Bsw[0][nblk][kc][off]) = hi;
            *(__nv_bfloat16*)(&g_fc1Bsw[1][nblk][kc][off]) = lo;
        }
    }
}

// ---------------------------------------------------------------------------
// pv_mma: PVp[dir] = embed(row0=0) @ Wih^T, permuted cols, bf16 hi/lo 3-term.
// grid (8 nblk, 63 mtile, 2 dir), 256 thr. Single-stage (A needs conversion).
// ---------------------------------------------------------------------------
__global__ void __launch_bounds__(256) pv_mma(const float* __restrict__ embed)
{
    extern __shared__ unsigned char smraw[];
    uint32_t sb0 = smem_u32(smraw);
    uint32_t sb = (sb0 + 1023u) & ~1023u;
    unsigned char* smb = smraw + (sb - sb0);

    const int dir = blockIdx.z;
    const int nblk = blockIdx.x;
    const int m0 = blockIdx.y << 7;
    const int tid = threadIdx.x;
    const int lane = tid & 31, wid = tid >> 5;
    const int wm = wid >> 2, wn = wid & 3;

    float acc[4][4][4];
#pragma unroll
    for (int a = 0; a < 4; a++)
#pragma unroll
        for (int b = 0; b < 4; b++)
#pragma unroll
            for (int c = 0; c < 4; c++) acc[a][b][c] = 0.f;

    const uint32_t aBaseH = sb, aBaseL = sb + 16384u, bBaseH = sb + 32768u, bBaseL = sb + 49152u;
    const int arow = (wm << 6) + (lane & 15);
    const int atop = (lane >> 4) << 4;
    const int brow = (wn << 5) + (lane & 7) + ((lane & 16) ? 8 : 0);
    const int btop = (lane & 8) ? 16 : 0;

    for (int kc = 0; kc < 4; kc++) {
#pragma unroll
        for (int i = 0; i < 4; i++) {
            int u = tid + (i << 8);
            int r = u >> 3, c8 = u & 7;
            int g = m0 + r;
            float vals[8];
            if (g == 0 || g >= Vv) {
#pragma unroll
                for (int j = 0; j < 8; j++) vals[j] = 0.f;
            } else {
                float4 v0 = *(const float4*)(embed + (size_t)g * Ee + (kc << 6) + (c8 << 3));
                float4 v1 = *(const float4*)(embed + (size_t)g * Ee + (kc << 6) + (c8 << 3) + 4);
                vals[0] = v0.x; vals[1] = v0.y; vals[2] = v0.z; vals[3] = v0.w;
                vals[4] = v1.x; vals[5] = v1.y; vals[6] = v1.z; vals[7] = v1.w;
            }
            uint4 hi, lo;
            split8(vals, &hi, &lo);
            uint32_t off = swz128((uint32_t)r * 128u + ((uint32_t)c8 << 4));
            *(uint4*)(smb + off) = hi;
            *(uint4*)(smb + 16384u + off) = lo;
        }
#pragma unroll
        for (int hl = 0; hl < 2; hl++) {
            const uint4* src = (const uint4*)&g_BswIH[dir][hl][nblk][kc][0];
            uint4* dst = (uint4*)(smb + 32768 + hl * 16384);
#pragma unroll
            for (int i = 0; i < 4; i++) dst[tid + (i << 8)] = src[tid + (i << 8)];
        }
        __syncthreads();

#pragma unroll
        for (int ks = 0; ks < 4; ks++) {
            const uint32_t kbyte = (uint32_t)ks << 5;
            uint32_t ah[4][4], al[4][4], bh[8], bl[8];
#pragma unroll
            for (int mi = 0; mi < 4; mi++) {
                uint32_t off = swz128((uint32_t)(arow + mi * 16) * 128u + kbyte + (uint32_t)atop);
                ldsm4(ah[mi], aBaseH + off);
                ldsm4(al[mi], aBaseL + off);
            }
#pragma unroll
            for (int bi = 0; bi < 2; bi++) {
                uint32_t off = swz128((uint32_t)(brow + bi * 16) * 128u + kbyte + (uint32_t)btop);
                ldsm4(bh + bi * 4, bBaseH + off);
                ldsm4(bl + bi * 4, bBaseL + off);
            }
#pragma unroll
            for (int mi = 0; mi < 4; mi++)
#pragma unroll
                for (int ni = 0; ni < 4; ni++) {
                    mma_bf16(acc[mi][ni], ah[mi], bh + ni * 2);
                    mma_bf16(acc[mi][ni], ah[mi], bl + ni * 2);
                    mma_bf16(acc[mi][ni], al[mi], bh + ni * 2);
                }
        }
        __syncthreads();
    }

    float* out = g_PVp[dir];
#pragma unroll
    for (int mi = 0; mi < 4; mi++) {
        int r0 = m0 + (wm << 6) + mi * 16 + (lane >> 2);
#pragma unroll
        for (int ni = 0; ni < 4; ni++) {
            int c0 = (nblk << 7) + (wn << 5) + ni * 8 + ((lane & 3) << 1);
            if (r0 < Vv)
                *(float2*)(out + (size_t)r0 * G4H + c0) = make_float2(acc[mi][ni][0], acc[mi][ni][1]);
            if (r0 + 8 < Vv)
                *(float2*)(out + (size_t)(r0 + 8) * G4H + c0) = make_float2(acc[mi][ni][2], acc[mi][ni][3]);
        }
    }
}

// ---------------------------------------------------------------------------
// zero h (buf0 hi/lo, both dirs) and c (both dirs)
// ---------------------------------------------------------------------------
__global__ void __launch_bounds__(256) zero_state()
{
    const int i = blockIdx.x * 256 + threadIdx.x;
    const uint4 z = make_uint4(0u, 0u, 0u, 0u);
    if (i < 2097152) {
        int slice = i >> 19;
        int dir = slice >> 1, hl = slice & 1;
        ((uint4*)g_hA[dir][0][hl])[i & 524287] = z;
    } else {
        int j = i - 2097152;
        int dir = j >> 20;
        ((uint4*)g_cst[dir])[j & 1048575] = z;
    }
}

// ---------------------------------------------------------------------------
// gates_mma: one LSTM step, both dirs. cp.async 2-stage pipeline; chained
// 3-term mma (R7 order); fused LSTM epilogue.
// smem: stage s at s*64KB: [A_hi 16K | A_lo 16K | B_hi 16K | B_lo 16K]; bias @128KB.
// ---------------------------------------------------------------------------
__global__ void __launch_bounds__(256) gates_mma(const int* __restrict__ x, int step)
{
    extern __shared__ unsigned char smraw[];
    uint32_t sb0 = smem_u32(smraw);
    uint32_t sb = (sb0 + 1023u) & ~1023u;
    unsigned char* smb = smraw + (sb - sb0);

    const int dir = blockIdx.z;
    const int nblk = blockIdx.x;
    const int m0 = blockIdx.y << 7;
    const int tid = threadIdx.x;
    const int lane = tid & 31, wid = tid >> 5;
    const int wm = wid >> 2, wn = wid & 3;
    const int buf = step & 1, nbuf = buf ^ 1;

    float* biasf = (float*)(smb + 131072);
    if (tid < 32)
        *(float4*)(biasf + (tid << 2)) = *(const float4*)(g_bsum[dir] + (nblk << 7) + (tid << 2));

    const uint4* srcA[2] = { (const uint4*)g_hA[dir][buf][0], (const uint4*)g_hA[dir][buf][1] };

    auto issue = [&](int kcx, int stg) {
        const uint32_t sbase = sb + (uint32_t)stg * 65536u;
#pragma unroll
        for (int hl = 0; hl < 2; hl++) {
            const uint4* src = srcA[hl];
#pragma unroll
            for (int i = 0; i < 4; i++) {
                int u = tid + (i << 8);
                int r = u >> 3, c16 = u & 7;
                uint32_t dst = sbase + (uint32_t)hl * 16384u +
                               swz128((uint32_t)r * 128u + ((uint32_t)c16 << 4));
                cpasync16(dst, &src[(size_t)(m0 + r) * 32 + (kcx << 3) + c16]);
            }
        }
#pragma unroll
        for (int hl = 0; hl < 2; hl++) {
            const unsigned char* src = &g_Bsw[dir][hl][nblk][kcx][0];
#pragma unroll
            for (int i = 0; i < 4; i++) {
                uint32_t o = ((uint32_t)tid + ((uint32_t)i << 8)) << 4;
                cpasync16(sbase + 32768u + (uint32_t)hl * 16384u + o, src + o);
            }
        }
        CPASYNC_COMMIT();
    };

    float acc[4][4][4];
#pragma unroll
    for (int a = 0; a < 4; a++)
#pragma unroll
        for (int b = 0; b < 4; b++)
#pragma unroll
            for (int c = 0; c < 4; c++) acc[a][b][c] = 0.f;

    const int arow = (wm << 6) + (lane & 15);
    const int atop = (lane >> 4) << 4;
    const int brow = (wn << 5) + (lane & 7) + ((lane & 16) ? 8 : 0);
    const int btop = (lane & 8) ? 16 : 0;

    issue(0, 0);
    for (int kc = 0; kc < 4; kc++) {
        const int stg = kc & 1;
        CPASYNC_WAIT_ALL();
        __syncthreads();
        if (kc < 3) issue(kc + 1, stg ^ 1);

        const uint32_t aH = sb + (uint32_t)stg * 65536u;
        const uint32_t aL = aH + 16384u, bH = aH + 32768u, bL = aH + 49152u;
#pragma unroll
        for (int ks = 0; ks < 4; ks++) {
            const uint32_t kbyte = (uint32_t)ks << 5;
            uint32_t ah[4][4], al[4][4], bh[8], bl[8];
#pragma unroll
            for (int mi = 0; mi < 4; mi++) {
                uint32_t off = swz128((uint32_t)(arow + mi * 16) * 128u + kbyte + (uint32_t)atop);
                ldsm4(ah[mi], aH + off);
                ldsm4(al[mi], aL + off);
            }
#pragma unroll
            for (int bi = 0; bi < 2; bi++) {
                uint32_t off = swz128((uint32_t)(brow + bi * 16) * 128u + kbyte + (uint32_t)btop);
                ldsm4(bh + bi * 4, bH + off);
                ldsm4(bl + bi * 4, bL + off);
            }
#pragma unroll
            for (int mi = 0; mi < 4; mi++)
#pragma unroll
                for (int ni = 0; ni < 4; ni++) {
                    mma_bf16(acc[mi][ni], ah[mi], bh + ni * 2);
                    mma_bf16(acc[mi][ni], ah[mi], bl + ni * 2);
                    mma_bf16(acc[mi][ni], al[mi], bh + ni * 2);
                }
        }
        __syncthreads();
    }

    // stage accumulators into smem (stage-0 region; safe after final sync)
    float* Acc = (float*)smb;
#pragma unroll
    for (int mi = 0; mi < 4; mi++)
#pragma unroll
        for (int ni = 0; ni < 4; ni++) {
            int r0 = (wm << 6) + mi * 16 + (lane >> 2);
            int c0 = (wn << 5) + ni * 8 + ((lane & 3) << 1);
            *(float2*)(Acc + r0 * 128 + c0) = make_float2(acc[mi][ni][0], acc[mi][ni][1]);
            *(float2*)(Acc + (r0 + 8) * 128 + c0) = make_float2(acc[mi][ni][2], acc[mi][ni][3]);
        }
    __syncthreads();

    // fused epilogue: 2 threads per row, 16 units each
    const int row_l = tid >> 1;
    const int half = tid & 1;
    const int row = m0 + row_l;
    const int t = row & (Ss - 1), bidx = row >> 10;
    const int tp = dir ? (t + WSw - step) : (t - WSw + step);
    const bool valid = ((unsigned)tp < (unsigned)Ss);
    const int tok = valid ? x[(bidx << 10) + tp] : 0;
    const bool finalstep = (step == WSw);

    const float4* accu = (const float4*)(Acc + row_l * 128 + (half << 6));
    const float4* bsu  = (const float4*)(biasf + (half << 6));
    const float4* pvu  = (const float4*)(g_PVp[dir] + (size_t)tok * G4H + (nblk << 7) + (half << 6));
    float4* cp = (float4*)(g_cst[dir] + (size_t)row * Hh + (nblk << 5) + (half << 4));
    const int colbase = (nblk << 5) + (half << 4);
    __nv_bfloat16* hip = g_hA[dir][nbuf][0] + (size_t)row * Hh + colbase;
    __nv_bfloat16* lop = g_hA[dir][nbuf][1] + (size_t)row * Hh + colbase;
    __nv_bfloat16* fHp = g_fcA[0] + (size_t)row * FHh + dir * Hh + colbase;
    __nv_bfloat16* fLp = g_fcA[1] + (size_t)row * FHh + dir * Hh + colbase;

    uint32_t hwH[8], hwL[8];
    uint32_t fwH[8], fwL[8];
#pragma unroll
    for (int g4 = 0; g4 < 4; g4++) {
        float4 cv = cp[g4];
        float cin[4] = {cv.x, cv.y, cv.z, cv.w};
        float ho[4];
#pragma unroll
        for (int j = 0; j < 4; j++) {
            int u = g4 * 4 + j;
            float4 gq = accu[u];
            float4 bq = bsu[u];
            float pi = gq.x + bq.x, pf = gq.y + bq.y, pg = gq.z + bq.z, po = gq.w + bq.w;
            if (valid) {
                float4 pq = pvu[u];
                pi += pq.x; pf += pq.y; pg += pq.z; po += pq.w;
            }
            float iv = sigmoidf_(pi), fv = sigmoidf_(pf), gv = tanhf(pg), ov = sigmoidf_(po);
            float cn = fv * cin[j] + iv * gv;
            cin[j] = cn;
            ho[j] = ov * tanhf(cn);
        }
        cp[g4] = make_float4(cin[0], cin[1], cin[2], cin[3]);
        __nv_bfloat16 h0 = __float2bfloat16(ho[0]), h1 = __float2bfloat16(ho[1]);
        __nv_bfloat16 h2 = __float2bfloat16(ho[2]), h3 = __float2bfloat16(ho[3]);
        hwH[g4 * 2 + 0] = packbf(h0, h1);
        hwH[g4 * 2 + 1] = packbf(h2, h3);
        hwL[g4 * 2 + 0] = packbf(__float2bfloat16(ho[0] - __bfloat162float(h0)),
                                 __float2bfloat16(ho[1] - __bfloat162float(h1)));
        hwL[g4 * 2 + 1] = packbf(__float2bfloat16(ho[2] - __bfloat162float(h2)),
                                 __float2bfloat16(ho[3] - __bfloat162float(h3)));
        if (finalstep) {
            float lk[4];
#pragma unroll
            for (int j = 0; j < 4; j++) lk[j] = leakyf_(ho[j]);
            __nv_bfloat16 f0 = __float2bfloat16(lk[0]), f1 = __float2bfloat16(lk[1]);
            __nv_bfloat16 f2 = __float2bfloat16(lk[2]), f3 = __float2bfloat16(lk[3]);
            fwH[g4 * 2 + 0] = packbf(f0, f1);
            fwH[g4 * 2 + 1] = packbf(f2, f3);
            fwL[g4 * 2 + 0] = packbf(__float2bfloat16(lk[0] - __bfloat162float(f0)),
                                     __float2bfloat16(lk[1] - __bfloat162float(f1)));
            fwL[g4 * 2 + 1] = packbf(__float2bfloat16(lk[2] - __bfloat162float(f2)),
                                     __float2bfloat16(lk[3] - __bfloat162float(f3)));
        }
    }
    *(uint4*)hip       = make_uint4(hwH[0], hwH[1], hwH[2], hwH[3]);
    *(uint4*)(hip + 8) = make_uint4(hwH[4], hwH[5], hwH[6], hwH[7]);
    *(uint4*)lop       = make_uint4(hwL[0], hwL[1], hwL[2], hwL[3]);
    *(uint4*)(lop + 8) = make_uint4(hwL[4], hwL[5], hwL[6], hwL[7]);
    if (finalstep) {
        *(uint4*)fHp       = make_uint4(fwH[0], fwH[1], fwH[2], fwH[3]);
        *(uint4*)(fHp + 8) = make_uint4(fwH[4], fwH[5], fwH[6], fwH[7]);
        *(uint4*)fLp       = make_uint4(fwL[0], fwL[1], fwL[2], fwL[3]);
        *(uint4*)(fLp + 8) = make_uint4(fwL[4], fwL[5], fwL[6], fwL[7]);
    }
}

// ---------------------------------------------------------------------------
// fc1_mma: g_fc1 = leaky( fcA @ fc1_w^T + fc1_b ), cp.async 2-stage pipeline.
// grid (4 nblk, 128 mtile), 256 thr. K=512 in 8 chunks.
// ---------------------------------------------------------------------------
__global__ void __launch_bounds__(256) fc1_mma(const float* __restrict__ fc1_b)
{
    extern __shared__ unsigned char smraw[];
    uint32_t sb0 = smem_u32(smraw);
    uint32_t sb = (sb0 + 1023u) & ~1023u;
    unsigned char* smb = smraw + (sb - sb0);

    const int nblk = blockIdx.x;
    const int m0 = blockIdx.y << 7;
    const int tid = threadIdx.x;
    const int lane = tid & 31, wid = tid >> 5;
    const int wm = wid >> 2, wn = wid & 3;

    float* biasf = (float*)(smb + 131072);
    if (tid < 32)
        *(float4*)(biasf + (tid << 2)) = *(const float4*)(fc1_b + (nblk << 7) + (tid << 2));

    auto issue = [&](int kcx, int stg) {
        const uint32_t sbase = sb + (uint32_t)stg * 65536u;
#pragma unroll
        for (int hl = 0; hl < 2; hl++) {
            const uint4* src = (const uint4*)g_fcA[hl];
#pragma unroll
            for (int i = 0; i < 4; i++) {
                int u = tid + (i << 8);
                int r = u >> 3, c16 = u & 7;
                uint32_t dst = sbase + (uint32_t)hl * 16384u +
                               swz128((uint32_t)r * 128u + ((uint32_t)c16 << 4));
                cpasync16(dst, &src[(size_t)(m0 + r) * 64 + (kcx << 3) + c16]);
            }
        }
#pragma unroll
        for (int hl = 0; hl < 2; hl++) {
            const unsigned char* src = &g_fc1Bsw[hl][nblk][kcx][0];
#pragma unroll
            for (int i = 0; i < 4; i++) {
                uint32_t o = ((uint32_t)tid + ((uint32_t)i << 8)) << 4;
                cpasync16(sbase + 32768u + (uint32_t)hl * 16384u + o, src + o);
            }
        }
        CPASYNC_COMMIT();
    };

    float acc[4][4][4];
#pragma unroll
    for (int a = 0; a < 4; a++)
#pragma unroll
        for (int b = 0; b < 4; b++)
#pragma unroll
            for (int c = 0; c < 4; c++) acc[a][b][c] = 0.f;

    const int arow = (wm << 6) + (lane & 15);
    const int atop = (lane >> 4) << 4;
    const int brow = (wn << 5) + (lane & 7) + ((lane & 16) ? 8 : 0);
    const int btop = (lane & 8) ? 16 : 0;

    issue(0, 0);
    for (int kc = 0; kc < 8; kc++) {
        const int stg = kc & 1;
        CPASYNC_WAIT_ALL();
        __syncthreads();
        if (kc < 7) issue(kc + 1, stg ^ 1);

        const uint32_t aH = sb + (uint32_t)stg * 65536u;
        const uint32_t aL = aH + 16384u, bH = aH + 32768u, bL = aH + 49152u;
#pragma unroll
        for (int ks = 0; ks < 4; ks++) {
            const uint32_t kbyte = (uint32_t)ks << 5;
            uint32_t ah[4][4], al[4][4], bh[8], bl[8];
#pragma unroll
            for (int mi = 0; mi < 4; mi++) {
                uint32_t off = swz128((uint32_t)(arow + mi * 16) * 128u + kbyte + (uint32_t)atop);
                ldsm4(ah[mi], aH + off);
                ldsm4(al[mi], aL + off);
            }
#pragma unroll
            for (int bi = 0; bi < 2; bi++) {
                uint32_t off = swz128((uint32_t)(brow + bi * 16) * 128u + kbyte + (uint32_t)btop);
                ldsm4(bh + bi * 4, bH + off);
                ldsm4(bl + bi * 4, bL + off);
            }
#pragma unroll
            for (int mi = 0; mi < 4; mi++)
#pragma unroll
                for (int ni = 0; ni < 4; ni++) {
                    mma_bf16(acc[mi][ni], ah[mi], bh + ni * 2);
                    mma_bf16(acc[mi][ni], ah[mi], bl + ni * 2);
                    mma_bf16(acc[mi][ni], al[mi], bh + ni * 2);
                }
        }
        __syncthreads();
    }

    // epilogue: bias + leaky, direct register store
#pragma unroll
    for (int mi = 0; mi < 4; mi++) {
        int r0 = m0 + (wm << 6) + mi * 16 + (lane >> 2);
#pragma unroll
        for (int ni = 0; ni < 4; ni++) {
            int cl = (wn << 5) + ni * 8 + ((lane & 3) << 1);
            int c0 = (nblk << 7) + cl;
            float b0 = biasf[cl], b1 = biasf[cl + 1];
            *(float2*)(g_fc1 + (size_t)r0 * FHh + c0) =
                make_float2(leakyf_(acc[mi][ni][0] + b0), leakyf_(acc[mi][ni][1] + b1));
            *(float2*)(g_fc1 + (size_t)(r0 + 8) * FHh + c0) =
                make_float2(leakyf_(acc[mi][ni][2] + b0), leakyf_(acc[mi][ni][3] + b1));
        }
    }
}

// ---------------------------------------------------------------------------
// fc2: out[n] = sigmoid( g_fc1[n] . fc2_w + fc2_b )
// ---------------------------------------------------------------------------
__global__ void __launch_bounds__(128) fc2_kernel(const float* __restrict__ w,
                                                  const float* __restrict__ b,
                                                  float* __restrict__ out)
{
    const int n = blockIdx.x;
    const int t = threadIdx.x;
    const float4 a = ((const float4*)(g_fc1 + (size_t)n * FHh))[t];
    const float4 wv = ((const float4*)w)[t];
    float s = a.x * wv.x + a.y * wv.y + a.z * wv.z + a.w * wv.w;
#pragma unroll
    for (int o = 16; o > 0; o >>= 1) s += __shfl_xor_sync(0xffffffffu, s, o);
    __shared__ float ws[4];
    if ((t & 31) == 0) ws[t >> 5] = s;
    __syncthreads();
    if (t == 0) {
        const float tot = ws[0] + ws[1] + ws[2] + ws[3];
        out[n] = 1.0f / (1.0f + expf(-(tot + b[0])));
    }
}

// ---------------------------------------------------------------------------
extern "C" void kernel_launch(void* const* d_in, const int* in_sizes, int n_in,
                              void* d_out, int out_size)
{
    const int*   x      = (const int*)  d_in[0];
    const float* embed  = (const float*)d_in[1];
    const float* Wih_f  = (const float*)d_in[2];
    const float* Whh_f  = (const float*)d_in[3];
    const float* bih_f  = (const float*)d_in[4];
    const float* bhh_f  = (const float*)d_in[5];
    const float* Wih_b  = (const float*)d_in[6];
    const float* Whh_b  = (const float*)d_in[7];
    const float* bih_b  = (const float*)d_in[8];
    const float* bhh_b  = (const float*)d_in[9];
    const float* fc1_w  = (const float*)d_in[10];
    const float* fc1_b  = (const float*)d_in[11];
    const float* fc2_w  = (const float*)d_in[12];
    const float* fc2_b  = (const float*)d_in[13];
    float* out = (float*)d_out;

    cudaFuncSetAttribute(gates_mma, cudaFuncAttributeMaxDynamicSharedMemorySize, PIPE_SMEM);
    cudaFuncSetAttribute(fc1_mma,   cudaFuncAttributeMaxDynamicSharedMemorySize, PIPE_SMEM);
    cudaFuncSetAttribute(pv_mma,    cudaFuncAttributeMaxDynamicSharedMemorySize, PV_SMEM);

    prep_all<<<640, 256>>>(Whh_f, Whh_b, Wih_f, Wih_b, fc1_w,
                           bih_f, bhh_f, bih_b, bhh_b);
    pv_mma<<<dim3(8, 63, 2), 256, PV_SMEM>>>(embed);
    zero_state<<<16384, 256>>>();

    for (int k = 0; k <= WSw; k++) {
        gates_mma<<<dim3(8, NTOK / 128, 2), 256, PIPE_SMEM>>>(x, k);
    }

    fc1_mma<<<dim3(4, 128), 256, PIPE_SMEM>>>(fc1_b);
    fc2_kernel<<<NTOK, 128>>>(fc2_w, fc2_b, out);
}

// round 10
// speedup vs baseline: 1.1043x; 1.0279x over previous
#include <cuda_runtime.h>
#include <cuda_bf16.h>
#include <math.h>
#include <stdint.h>

#define Bb   16
#define Ss   1024
#define Ee   256
#define Hh   256
#define FHh  512
#define Vv   8000
#define WSw  5
#define NTOK (Bb*Ss)     /* 16384 */
#define G4H  (4*Hh)      /* 1024  */

// ---------------- scratch (device globals; no dynamic allocation) ----------
__device__ float g_PVp[2][(size_t)Vv * G4H];            // permuted-col input projections
__device__ __nv_bfloat16 g_hA[2][2][2][(size_t)NTOK * Hh];  // [dir][pingpong][hi/lo] h bf16
__device__ float g_cst[2][(size_t)NTOK * Hh];           // [dir] c state
__device__ __nv_bfloat16 g_fcA[2][(size_t)NTOK * FHh];  // [hi/lo] leaky(h) concat, fc1 A
__device__ float g_fc1[(size_t)NTOK * FHh];
// pre-split bf16 hi/lo, col-permuted, pre-swizzled weight tiles (128 rows x 64 k = 16KB)
__device__ unsigned char g_Bsw[2][2][8][4][16384];      // Whh  [dir][hl][nblk][kc]
__device__ unsigned char g_BswIH[2][2][8][4][16384];    // Wih  [dir][hl][nblk][kc]
__device__ unsigned char g_fc1Bsw[2][4][8][16384];      // fc1_w [hl][nblk][kc]
__device__ float g_bsum[2][G4H];                        // permuted bih+bhh

__device__ __forceinline__ float sigmoidf_(float x) { return 1.0f / (1.0f + expf(-x)); }
__device__ __forceinline__ float leakyf_(float x)   { return x > 0.0f ? x : 0.01f * x; }
__device__ __forceinline__ uint32_t swz128(uint32_t off) { return off ^ ((off >> 3) & 0x70); }
__device__ __forceinline__ uint32_t smem_u32(const void* p) {
    uint32_t a;
    asm("{ .reg .u64 t; cvta.to.shared.u64 t, %1; cvt.u32.u64 %0, t; }" : "=r"(a) : "l"(p));
    return a;
}
__device__ __forceinline__ void ldsm4(uint32_t* r, uint32_t addr) {
    asm volatile("ldmatrix.sync.aligned.m8n8.x4.shared.b16 {%0,%1,%2,%3}, [%4];"
        : "=r"(r[0]), "=r"(r[1]), "=r"(r[2]), "=r"(r[3]) : "r"(addr));
}
__device__ __forceinline__ void mma_bf16(float* d, const uint32_t* a, const uint32_t* b) {
    asm volatile("mma.sync.aligned.m16n8k16.row.col.f32.bf16.bf16.f32 "
        "{%0,%1,%2,%3}, {%4,%5,%6,%7}, {%8,%9}, {%0,%1,%2,%3};"
        : "+f"(d[0]), "+f"(d[1]), "+f"(d[2]), "+f"(d[3])
        : "r"(a[0]), "r"(a[1]), "r"(a[2]), "r"(a[3]), "r"(b[0]), "r"(b[1]));
}
__device__ __forceinline__ void cpasync16(uint32_t dst, const void* src) {
    asm volatile("cp.async.cg.shared.global [%0], [%1], 16;" :: "r"(dst), "l"(src));
}
#define CPASYNC_COMMIT() asm volatile("cp.async.commit_group;" ::: "memory")
#define CPASYNC_WAIT_ALL() asm volatile("cp.async.wait_group 0;" ::: "memory")

__device__ __forceinline__ uint32_t packbf(__nv_bfloat16 a, __nv_bfloat16 b) {
    unsigned short ua = *(unsigned short*)&a, ub = *(unsigned short*)&b;
    return (uint32_t)ua | ((uint32_t)ub << 16);
}
__device__ __forceinline__ void split8(const float* v, uint4* hi, uint4* lo) {
    __nv_bfloat16 h[8];
    uint32_t hw[4], lw[4];
#pragma unroll
    for (int j = 0; j < 8; j++) h[j] = __float2bfloat16(v[j]);
#pragma unroll
    for (int j = 0; j < 4; j++) {
        hw[j] = packbf(h[2 * j], h[2 * j + 1]);
        lw[j] = packbf(__float2bfloat16(v[2 * j]     - __bfloat162float(h[2 * j])),
                       __float2bfloat16(v[2 * j + 1] - __bfloat162float(h[2 * j + 1])));
    }
    *hi = make_uint4(hw[0], hw[1], hw[2], hw[3]);
    *lo = make_uint4(lw[0], lw[1], lw[2], lw[3]);
}

#define PV_SMEM  (1024 + 65536 + 512)
#define SB_SMEM  (1024 + 65536 + 512)   /* single 64KB stage + bias */

// ---------------------------------------------------------------------------
// prep_all: blocks [0,256) Whh split (+bias), [256,512) Wih split,
//           [512,640) fc1_w split. Permutation p = unit*4+gate for Whh/Wih.
// ---------------------------------------------------------------------------
__global__ void __launch_bounds__(256) prep_all(const float* __restrict__ Whf, const float* __restrict__ Whb,
                                                const float* __restrict__ Wif, const float* __restrict__ Wib,
                                                const float* __restrict__ fc1w,
                                                const float* __restrict__ bihf, const float* __restrict__ bhhf,
                                                const float* __restrict__ bihb, const float* __restrict__ bhhb)
{
    const int blk = blockIdx.x;
    const int tid = threadIdx.x;
    if (blk < 512) {
        const int sect = blk >> 8;                       // 0 = Whh, 1 = Wih
        int idx = (blk & 255) * 256 + tid;               // 65536 per section
        int dir = idx >> 15;
        int r = idx & 32767;
        int n = r >> 5;
        int k8 = (r & 31) << 3;
        const float* W = sect ? (dir ? Wib : Wif) : (dir ? Whb : Whf);
        int p = ((n & 255) << 2) | (n >> 8);             // unit*4 + gate
        int nblk = p >> 7, prow = p & 127;
        float4 v0 = *(const float4*)(W + (size_t)n * Hh + k8);
        float4 v1 = *(const float4*)(W + (size_t)n * Hh + k8 + 4);
        float vals[8] = {v0.x, v0.y, v0.z, v0.w, v1.x, v1.y, v1.z, v1.w};
#pragma unroll
        for (int j = 0; j < 8; j++) {
            int k = k8 + j;
            int kc = k >> 6, kb = k & 63;
            uint32_t off = swz128((uint32_t)prow * 128u + (uint32_t)kb * 2u);
            __nv_bfloat16 hi = __float2bfloat16(vals[j]);
            __nv_bfloat16 lo = __float2bfloat16(vals[j] - __bfloat162float(hi));
            if (sect == 0) {
                *(__nv_bfloat16*)(&g_Bsw[dir][0][nblk][kc][off]) = hi;
                *(__nv_bfloat16*)(&g_Bsw[dir][1][nblk][kc][off]) = lo;
            } else {
                *(__nv_bfloat16*)(&g_BswIH[dir][0][nblk][kc][off]) = hi;
                *(__nv_bfloat16*)(&g_BswIH[dir][1][nblk][kc][off]) = lo;
            }
        }
        if (sect == 0 && k8 == 0) {
            const float* bi = dir ? bihb : bihf;
            const float* bh = dir ? bhhb : bhhf;
            g_bsum[dir][p] = bi[n] + bh[n];
        }
    } else {
        int idx = (blk - 512) * 256 + tid;               // 32768 threads
        int n = idx >> 6;                                // 0..511
        int k8 = (idx & 63) << 3;
        int nblk = n >> 7, prow = n & 127;
        float4 v0 = *(const float4*)(fc1w + (size_t)n * FHh + k8);
        float4 v1 = *(const float4*)(fc1w + (size_t)n * FHh + k8 + 4);
        float vals[8] = {v0.x, v0.y, v0.z, v0.w, v1.x, v1.y, v1.z, v1.w};
#pragma unroll
        for (int j = 0; j < 8; j++) {
            int k = k8 + j;
            int kc = k >> 6, kb = k & 63;
            uint32_t off = swz128((uint32_t)prow * 128u + (uint32_t)kb * 2u);
            __nv_bfloat16 hi = __float2bfloat16(vals[j]);
            __nv_bfloat16 lo = __float2bfloat16(vals[j] - __bfloat162float(hi));
            *(__nv_bfloat16*)(&g_fc1Bsw[0][nblk][kc][off]) = hi;
            *(__nv_bfloat16*)(&g_fc1Bsw[1][nblk][kc][off]) = lo;
        }
    }
}

// ---------------------------------------------------------------------------
// pv_mma: PVp[dir] = embed(row0=0) @ Wih^T, permuted cols, bf16 hi/lo 3-term.
// grid (8 nblk, 63 mtile, 2 dir), 256 thr.
// ---------------------------------------------------------------------------
__global__ void __launch_bounds__(256) pv_mma(const float* __restrict__ embed)
{
    extern __shared__ unsigned char smraw[];
    uint32_t sb0 = smem_u32(smraw);
    uint32_t sb = (sb0 + 1023u) & ~1023u;
    unsigned char* smb = smraw + (sb - sb0);

    const int dir = blockIdx.z;
    const int nblk = blockIdx.x;
    const int m0 = blockIdx.y << 7;
    const int tid = threadIdx.x;
    const int lane = tid & 31, wid = tid >> 5;
    const int wm = wid >> 2, wn = wid & 3;

    float acc[4][4][4];
#pragma unroll
    for (int a = 0; a < 4; a++)
#pragma unroll
        for (int b = 0; b < 4; b++)
#pragma unroll
            for (int c = 0; c < 4; c++) acc[a][b][c] = 0.f;

    const uint32_t aBaseH = sb, aBaseL = sb + 16384u, bBaseH = sb + 32768u, bBaseL = sb + 49152u;
    const int arow = (wm << 6) + (lane & 15);
    const int atop = (lane >> 4) << 4;
    const int brow = (wn << 5) + (lane & 7) + ((lane & 16) ? 8 : 0);
    const int btop = (lane & 8) ? 16 : 0;

    for (int kc = 0; kc < 4; kc++) {
#pragma unroll
        for (int i = 0; i < 4; i++) {
            int u = tid + (i << 8);
            int r = u >> 3, c8 = u & 7;
            int g = m0 + r;
            float vals[8];
            if (g == 0 || g >= Vv) {
#pragma unroll
                for (int j = 0; j < 8; j++) vals[j] = 0.f;
            } else {
                float4 v0 = *(const float4*)(embed + (size_t)g * Ee + (kc << 6) + (c8 << 3));
                float4 v1 = *(const float4*)(embed + (size_t)g * Ee + (kc << 6) + (c8 << 3) + 4);
                vals[0] = v0.x; vals[1] = v0.y; vals[2] = v0.z; vals[3] = v0.w;
                vals[4] = v1.x; vals[5] = v1.y; vals[6] = v1.z; vals[7] = v1.w;
            }
            uint4 hi, lo;
            split8(vals, &hi, &lo);
            uint32_t off = swz128((uint32_t)r * 128u + ((uint32_t)c8 << 4));
            *(uint4*)(smb + off) = hi;
            *(uint4*)(smb + 16384u + off) = lo;
        }
#pragma unroll
        for (int hl = 0; hl < 2; hl++) {
            const uint4* src = (const uint4*)&g_BswIH[dir][hl][nblk][kc][0];
            uint4* dst = (uint4*)(smb + 32768 + hl * 16384);
#pragma unroll
            for (int i = 0; i < 4; i++) dst[tid + (i << 8)] = src[tid + (i << 8)];
        }
        __syncthreads();

#pragma unroll
        for (int ks = 0; ks < 4; ks++) {
            const uint32_t kbyte = (uint32_t)ks << 5;
            uint32_t ah[4][4], al[4][4], bh[8], bl[8];
#pragma unroll
            for (int mi = 0; mi < 4; mi++) {
                uint32_t off = swz128((uint32_t)(arow + mi * 16) * 128u + kbyte + (uint32_t)atop);
                ldsm4(ah[mi], aBaseH + off);
                ldsm4(al[mi], aBaseL + off);
            }
#pragma unroll
            for (int bi = 0; bi < 2; bi++) {
                uint32_t off = swz128((uint32_t)(brow + bi * 16) * 128u + kbyte + (uint32_t)btop);
                ldsm4(bh + bi * 4, bBaseH + off);
                ldsm4(bl + bi * 4, bBaseL + off);
            }
#pragma unroll
            for (int mi = 0; mi < 4; mi++)
#pragma unroll
                for (int ni = 0; ni < 4; ni++) {
                    mma_bf16(acc[mi][ni], ah[mi], bh + ni * 2);
                    mma_bf16(acc[mi][ni], ah[mi], bl + ni * 2);
                    mma_bf16(acc[mi][ni], al[mi], bh + ni * 2);
                }
        }
        __syncthreads();
    }

    float* out = g_PVp[dir];
#pragma unroll
    for (int mi = 0; mi < 4; mi++) {
        int r0 = m0 + (wm << 6) + mi * 16 + (lane >> 2);
#pragma unroll
        for (int ni = 0; ni < 4; ni++) {
            int c0 = (nblk << 7) + (wn << 5) + ni * 8 + ((lane & 3) << 1);
            if (r0 < Vv)
                *(float2*)(out + (size_t)r0 * G4H + c0) = make_float2(acc[mi][ni][0], acc[mi][ni][1]);
            if (r0 + 8 < Vv)
                *(float2*)(out + (size_t)(r0 + 8) * G4H + c0) = make_float2(acc[mi][ni][2], acc[mi][ni][3]);
        }
    }
}

// ---------------------------------------------------------------------------
// zero h (buf0 hi/lo, both dirs) and c (both dirs)
// ---------------------------------------------------------------------------
__global__ void __launch_bounds__(256) zero_state()
{
    const int i = blockIdx.x * 256 + threadIdx.x;
    const uint4 z = make_uint4(0u, 0u, 0u, 0u);
    if (i < 2097152) {
        int slice = i >> 19;
        int dir = slice >> 1, hl = slice & 1;
        ((uint4*)g_hA[dir][0][hl])[i & 524287] = z;
    } else {
        int j = i - 2097152;
        int dir = j >> 20;
        ((uint4*)g_cst[dir])[j & 1048575] = z;
    }
}

// ---------------------------------------------------------------------------
// gates_mma: one LSTM step, both dirs. Single 64KB stage, cp.async loads,
// __launch_bounds__(256,2) for 2 CTAs/SM (inter-CTA overlap). Chained 3-term
// mma; fused LSTM epilogue.
// ---------------------------------------------------------------------------
__global__ void __launch_bounds__(256, 2) gates_mma(const int* __restrict__ x, int step)
{
    extern __shared__ unsigned char smraw[];
    uint32_t sb0 = smem_u32(smraw);
    uint32_t sb = (sb0 + 1023u) & ~1023u;
    unsigned char* smb = smraw + (sb - sb0);

    const int dir = blockIdx.z;
    const int nblk = blockIdx.x;
    const int m0 = blockIdx.y << 7;
    const int tid = threadIdx.x;
    const int lane = tid & 31, wid = tid >> 5;
    const int wm = wid >> 2, wn = wid & 3;
    const int buf = step & 1, nbuf = buf ^ 1;

    float* biasf = (float*)(smb + 65536);
    if (tid < 32)
        *(float4*)(biasf + (tid << 2)) = *(const float4*)(g_bsum[dir] + (nblk << 7) + (tid << 2));

    const uint4* srcA[2] = { (const uint4*)g_hA[dir][buf][0], (const uint4*)g_hA[dir][buf][1] };

    float acc[4][4][4];
#pragma unroll
    for (int a = 0; a < 4; a++)
#pragma unroll
        for (int b = 0; b < 4; b++)
#pragma unroll
            for (int c = 0; c < 4; c++) acc[a][b][c] = 0.f;

    const int arow = (wm << 6) + (lane & 15);
    const int atop = (lane >> 4) << 4;
    const int brow = (wn << 5) + (lane & 7) + ((lane & 16) ? 8 : 0);
    const int btop = (lane & 8) ? 16 : 0;

    for (int kc = 0; kc < 4; kc++) {
        // ---- issue loads into the single stage
#pragma unroll
        for (int hl = 0; hl < 2; hl++) {
            const uint4* src = srcA[hl];
#pragma unroll
            for (int i = 0; i < 4; i++) {
                int u = tid + (i << 8);
                int r = u >> 3, c16 = u & 7;
                uint32_t dst = sb + (uint32_t)hl * 16384u +
                               swz128((uint32_t)r * 128u + ((uint32_t)c16 << 4));
                cpasync16(dst, &src[(size_t)(m0 + r) * 32 + (kc << 3) + c16]);
            }
        }
#pragma unroll
        for (int hl = 0; hl < 2; hl++) {
            const unsigned char* src = &g_Bsw[dir][hl][nblk][kc][0];
#pragma unroll
            for (int i = 0; i < 4; i++) {
                uint32_t o = ((uint32_t)tid + ((uint32_t)i << 8)) << 4;
                cpasync16(sb + 32768u + (uint32_t)hl * 16384u + o, src + o);
            }
        }
        CPASYNC_COMMIT();
        CPASYNC_WAIT_ALL();
        __syncthreads();

        const uint32_t aH = sb, aL = sb + 16384u, bH = sb + 32768u, bL = sb + 49152u;
#pragma unroll
        for (int ks = 0; ks < 4; ks++) {
            const uint32_t kbyte = (uint32_t)ks << 5;
            uint32_t ah[4][4], al[4][4], bh[8], bl[8];
#pragma unroll
            for (int mi = 0; mi < 4; mi++) {
                uint32_t off = swz128((uint32_t)(arow + mi * 16) * 128u + kbyte + (uint32_t)atop);
                ldsm4(ah[mi], aH + off);
                ldsm4(al[mi], aL + off);
            }
#pragma unroll
            for (int bi = 0; bi < 2; bi++) {
                uint32_t off = swz128((uint32_t)(brow + bi * 16) * 128u + kbyte + (uint32_t)btop);
                ldsm4(bh + bi * 4, bH + off);
                ldsm4(bl + bi * 4, bL + off);
            }
#pragma unroll
            for (int mi = 0; mi < 4; mi++)
#pragma unroll
                for (int ni = 0; ni < 4; ni++) {
                    mma_bf16(acc[mi][ni], ah[mi], bh + ni * 2);
                    mma_bf16(acc[mi][ni], ah[mi], bl + ni * 2);
                    mma_bf16(acc[mi][ni], al[mi], bh + ni * 2);
                }
        }
        __syncthreads();
    }

    // stage accumulators into smem (reuse tile region; safe after final sync)
    float* Acc = (float*)smb;
#pragma unroll
    for (int mi = 0; mi < 4; mi++)
#pragma unroll
        for (int ni = 0; ni < 4; ni++) {
            int r0 = (wm << 6) + mi * 16 + (lane >> 2);
            int c0 = (wn << 5) + ni * 8 + ((lane & 3) << 1);
            *(float2*)(Acc + r0 * 128 + c0) = make_float2(acc[mi][ni][0], acc[mi][ni][1]);
            *(float2*)(Acc + (r0 + 8) * 128 + c0) = make_float2(acc[mi][ni][2], acc[mi][ni][3]);
        }
    __syncthreads();

    // fused epilogue: 2 threads per row, 16 units each
    const int row_l = tid >> 1;
    const int half = tid & 1;
    const int row = m0 + row_l;
    const int t = row & (Ss - 1), bidx = row >> 10;
    const int tp = dir ? (t + WSw - step) : (t - WSw + step);
    const bool valid = ((unsigned)tp < (unsigned)Ss);
    const int tok = valid ? x[(bidx << 10) + tp] : 0;
    const bool finalstep = (step == WSw);

    const float4* accu = (const float4*)(Acc + row_l * 128 + (half << 6));
    const float4* bsu  = (const float4*)(biasf + (half << 6));
    const float4* pvu  = (const float4*)(g_PVp[dir] + (size_t)tok * G4H + (nblk << 7) + (half << 6));
    float4* cp = (float4*)(g_cst[dir] + (size_t)row * Hh + (nblk << 5) + (half << 4));
    const int colbase = (nblk << 5) + (half << 4);
    __nv_bfloat16* hip = g_hA[dir][nbuf][0] + (size_t)row * Hh + colbase;
    __nv_bfloat16* lop = g_hA[dir][nbuf][1] + (size_t)row * Hh + colbase;
    __nv_bfloat16* fHp = g_fcA[0] + (size_t)row * FHh + dir * Hh + colbase;
    __nv_bfloat16* fLp = g_fcA[1] + (size_t)row * FHh + dir * Hh + colbase;

    uint32_t hwH[8], hwL[8];
    uint32_t fwH[8], fwL[8];
#pragma unroll
    for (int g4 = 0; g4 < 4; g4++) {
        float4 cv = cp[g4];
        float cin[4] = {cv.x, cv.y, cv.z, cv.w};
        float ho[4];
#pragma unroll
        for (int j = 0; j < 4; j++) {
            int u = g4 * 4 + j;
            float4 gq = accu[u];
            float4 bq = bsu[u];
            float pi = gq.x + bq.x, pf = gq.y + bq.y, pg = gq.z + bq.z, po = gq.w + bq.w;
            if (valid) {
                float4 pq = pvu[u];
                pi += pq.x; pf += pq.y; pg += pq.z; po += pq.w;
            }
            float iv = sigmoidf_(pi), fv = sigmoidf_(pf), gv = tanhf(pg), ov = sigmoidf_(po);
            float cn = fv * cin[j] + iv * gv;
            cin[j] = cn;
            ho[j] = ov * tanhf(cn);
        }
        cp[g4] = make_float4(cin[0], cin[1], cin[2], cin[3]);
        __nv_bfloat16 h0 = __float2bfloat16(ho[0]), h1 = __float2bfloat16(ho[1]);
        __nv_bfloat16 h2 = __float2bfloat16(ho[2]), h3 = __float2bfloat16(ho[3]);
        hwH[g4 * 2 + 0] = packbf(h0, h1);
        hwH[g4 * 2 + 1] = packbf(h2, h3);
        hwL[g4 * 2 + 0] = packbf(__float2bfloat16(ho[0] - __bfloat162float(h0)),
                                 __float2bfloat16(ho[1] - __bfloat162float(h1)));
        hwL[g4 * 2 + 1] = packbf(__float2bfloat16(ho[2] - __bfloat162float(h2)),
                                 __float2bfloat16(ho[3] - __bfloat162float(h3)));
        if (finalstep) {
            float lk[4];
#pragma unroll
            for (int j = 0; j < 4; j++) lk[j] = leakyf_(ho[j]);
            __nv_bfloat16 f0 = __float2bfloat16(lk[0]), f1 = __float2bfloat16(lk[1]);
            __nv_bfloat16 f2 = __float2bfloat16(lk[2]), f3 = __float2bfloat16(lk[3]);
            fwH[g4 * 2 + 0] = packbf(f0, f1);
            fwH[g4 * 2 + 1] = packbf(f2, f3);
            fwL[g4 * 2 + 0] = packbf(__float2bfloat16(lk[0] - __bfloat162float(f0)),
                                     __float2bfloat16(lk[1] - __bfloat162float(f1)));
            fwL[g4 * 2 + 1] = packbf(__float2bfloat16(lk[2] - __bfloat162float(f2)),
                                     __float2bfloat16(lk[3] - __bfloat162float(f3)));
        }
    }
    *(uint4*)hip       = make_uint4(hwH[0], hwH[1], hwH[2], hwH[3]);
    *(uint4*)(hip + 8) = make_uint4(hwH[4], hwH[5], hwH[6], hwH[7]);
    *(uint4*)lop       = make_uint4(hwL[0], hwL[1], hwL[2], hwL[3]);
    *(uint4*)(lop + 8) = make_uint4(hwL[4], hwL[5], hwL[6], hwL[7]);
    if (finalstep) {
        *(uint4*)fHp       = make_uint4(fwH[0], fwH[1], fwH[2], fwH[3]);
        *(uint4*)(fHp + 8) = make_uint4(fwH[4], fwH[5], fwH[6], fwH[7]);
        *(uint4*)fLp       = make_uint4(fwL[0], fwL[1], fwL[2], fwL[3]);
        *(uint4*)(fLp + 8) = make_uint4(fwL[4], fwL[5], fwL[6], fwL[7]);
    }
}

// ---------------------------------------------------------------------------
// fc1_mma: g_fc1 = leaky( fcA @ fc1_w^T + fc1_b ). Single stage, 2 CTAs/SM.
// grid (4 nblk, 128 mtile), 256 thr. K=512 in 8 chunks.
// ---------------------------------------------------------------------------
__global__ void __launch_bounds__(256, 2) fc1_mma(const float* __restrict__ fc1_b)
{
    extern __shared__ unsigned char smraw[];
    uint32_t sb0 = smem_u32(smraw);
    uint32_t sb = (sb0 + 1023u) & ~1023u;
    unsigned char* smb = smraw + (sb - sb0);

    const int nblk = blockIdx.x;
    const int m0 = blockIdx.y << 7;
    const int tid = threadIdx.x;
    const int lane = tid & 31, wid = tid >> 5;
    const int wm = wid >> 2, wn = wid & 3;

    float* biasf = (float*)(smb + 65536);
    if (tid < 32)
        *(float4*)(biasf + (tid << 2)) = *(const float4*)(fc1_b + (nblk << 7) + (tid << 2));

    float acc[4][4][4];
#pragma unroll
    for (int a = 0; a < 4; a++)
#pragma unroll
        for (int b = 0; b < 4; b++)
#pragma unroll
            for (int c = 0; c < 4; c++) acc[a][b][c] = 0.f;

    const int arow = (wm << 6) + (lane & 15);
    const int atop = (lane >> 4) << 4;
    const int brow = (wn << 5) + (lane & 7) + ((lane & 16) ? 8 : 0);
    const int btop = (lane & 8) ? 16 : 0;

    for (int kc = 0; kc < 8; kc++) {
#pragma unroll
        for (int hl = 0; hl < 2; hl++) {
            const uint4* src = (const uint4*)g_fcA[hl];
#pragma unroll
            for (int i = 0; i < 4; i++) {
                int u = tid + (i << 8);
                int r = u >> 3, c16 = u & 7;
                uint32_t dst = sb + (uint32_t)hl * 16384u +
                               swz128((uint32_t)r * 128u + ((uint32_t)c16 << 4));
                cpasync16(dst, &src[(size_t)(m0 + r) * 64 + (kc << 3) + c16]);
            }
        }
#pragma unroll
        for (int hl = 0; hl < 2; hl++) {
            const unsigned char* src = &g_fc1Bsw[hl][nblk][kc][0];
#pragma unroll
            for (int i = 0; i < 4; i++) {
                uint32_t o = ((uint32_t)tid + ((uint32_t)i << 8)) << 4;
                cpasync16(sb + 32768u + (uint32_t)hl * 16384u + o, src + o);
            }
        }
        CPASYNC_COMMIT();
        CPASYNC_WAIT_ALL();
        __syncthreads();

        const uint32_t aH = sb, aL = sb + 16384u, bH = sb + 32768u, bL = sb + 49152u;
#pragma unroll
        for (int ks = 0; ks < 4; ks++) {
            const uint32_t kbyte = (uint32_t)ks << 5;
            uint32_t ah[4][4], al[4][4], bh[8], bl[8];
#pragma unroll
            for (int mi = 0; mi < 4; mi++) {
                uint32_t off = swz128((uint32_t)(arow + mi * 16) * 128u + kbyte + (uint32_t)atop);
                ldsm4(ah[mi], aH + off);
                ldsm4(al[mi], aL + off);
            }
#pragma unroll
            for (int bi = 0; bi < 2; bi++) {
                uint32_t off = swz128((uint32_t)(brow + bi * 16) * 128u + kbyte + (uint32_t)btop);
                ldsm4(bh + bi * 4, bH + off);
                ldsm4(bl + bi * 4, bL + off);
            }
#pragma unroll
            for (int mi = 0; mi < 4; mi++)
#pragma unroll
                for (int ni = 0; ni < 4; ni++) {
                    mma_bf16(acc[mi][ni], ah[mi], bh + ni * 2);
                    mma_bf16(acc[mi][ni], ah[mi], bl + ni * 2);
                    mma_bf16(acc[mi][ni], al[mi], bh + ni * 2);
                }
        }
        __syncthreads();
    }

    // epilogue: bias + leaky, direct register store
#pragma unroll
    for (int mi = 0; mi < 4; mi++) {
        int r0 = m0 + (wm << 6) + mi * 16 + (lane >> 2);
#pragma unroll
        for (int ni = 0; ni < 4; ni++) {
            int cl = (wn << 5) + ni * 8 + ((lane & 3) << 1);
            int c0 = (nblk << 7) + cl;
            float b0 = biasf[cl], b1 = biasf[cl + 1];
            *(float2*)(g_fc1 + (size_t)r0 * FHh + c0) =
                make_float2(leakyf_(acc[mi][ni][0] + b0), leakyf_(acc[mi][ni][1] + b1));
            *(float2*)(g_fc1 + (size_t)(r0 + 8) * FHh + c0) =
                make_float2(leakyf_(acc[mi][ni][2] + b0), leakyf_(acc[mi][ni][3] + b1));
        }
    }
}

// ---------------------------------------------------------------------------
// fc2: out[n] = sigmoid( g_fc1[n] . fc2_w + fc2_b )
// ---------------------------------------------------------------------------
__global__ void __launch_bounds__(128) fc2_kernel(const float* __restrict__ w,
                                                  const float* __restrict__ b,
                                                  float* __restrict__ out)
{
    const int n = blockIdx.x;
    const int t = threadIdx.x;
    const float4 a = ((const float4*)(g_fc1 + (size_t)n * FHh))[t];
    const float4 wv = ((const float4*)w)[t];
    float s = a.x * wv.x + a.y * wv.y + a.z * wv.z + a.w * wv.w;
#pragma unroll
    for (int o = 16; o > 0; o >>= 1) s += __shfl_xor_sync(0xffffffffu, s, o);
    __shared__ float ws[4];
    if ((t & 31) == 0) ws[t >> 5] = s;
    __syncthreads();
    if (t == 0) {
        const float tot = ws[0] + ws[1] + ws[2] + ws[3];
        out[n] = 1.0f / (1.0f + expf(-(tot + b[0])));
    }
}

// ---------------------------------------------------------------------------
extern "C" void kernel_launch(void* const* d_in, const int* in_sizes, int n_in,
                              void* d_out, int out_size)
{
    const int*   x      = (const int*)  d_in[0];
    const float* embed  = (const float*)d_in[1];
    const float* Wih_f  = (const float*)d_in[2];
    const float* Whh_f  = (const float*)d_in[3];
    const float* bih_f  = (const float*)d_in[4];
    const float* bhh_f  = (const float*)d_in[5];
    const float* Wih_b  = (const float*)d_in[6];
    const float* Whh_b  = (const float*)d_in[7];
    const float* bih_b  = (const float*)d_in[8];
    const float* bhh_b  = (const float*)d_in[9];
    const float* fc1_w  = (const float*)d_in[10];
    const float* fc1_b  = (const float*)d_in[11];
    const float* fc2_w  = (const float*)d_in[12];
    const float* fc2_b  = (const float*)d_in[13];
    float* out = (float*)d_out;

    cudaFuncSetAttribute(gates_mma, cudaFuncAttributeMaxDynamicSharedMemorySize, SB_SMEM);
    cudaFuncSetAttribute(fc1_mma,   cudaFuncAttributeMaxDynamicSharedMemorySize, SB_SMEM);
    cudaFuncSetAttribute(pv_mma,    cudaFuncAttributeMaxDynamicSharedMemorySize, PV_SMEM);

    prep_all<<<640, 256>>>(Whh_f, Whh_b, Wih_f, Wih_b, fc1_w,
                           bih_f, bhh_f, bih_b, bhh_b);
    pv_mma<<<dim3(8, 63, 2), 256, PV_SMEM>>>(embed);
    zero_state<<<16384, 256>>>();

    for (int k = 0; k <= WSw; k++) {
        gates_mma<<<dim3(8, NTOK / 128, 2), 256, SB_SMEM>>>(x, k);
    }

    fc1_mma<<<dim3(4, 128), 256, SB_SMEM>>>(fc1_b);
    fc2_kernel<<<NTOK, 128>>>(fc2_w, fc2_b, out);
}

// round 11
// speedup vs baseline: 1.6062x; 1.4545x over previous
#include <cuda_runtime.h>
#include <cuda_fp16.h>
#include <math.h>
#include <stdint.h>

#define Bb   16
#define Ss   1024
#define Ee   256
#define Hh   256
#define FHh  512
#define Vv   8000
#define WSw  5
#define NTOK (Bb*Ss)     /* 16384 */
#define G4H  (4*Hh)      /* 1024  */

// ---------------- scratch (device globals; no dynamic allocation) ----------
__device__ float g_PVp[2][(size_t)Vv * G4H];            // permuted-col input projections
__device__ __half g_hA[2][2][(size_t)NTOK * Hh];        // [dir][pingpong] h as fp16
__device__ float g_cst[2][(size_t)NTOK * Hh];           // [dir] c state
__device__ __half g_fcA[(size_t)NTOK * FHh];            // leaky(h) concat, fc1 A (fp16)
__device__ float g_fc1[(size_t)NTOK * FHh];
// pre-split fp16 hi/lo, col-permuted, pre-swizzled weight tiles (128 rows x 64 k = 16KB)
__device__ unsigned char g_Bsw[2][2][8][4][16384];      // Whh  [dir][hl][nblk][kc]
__device__ unsigned char g_BswIH[2][2][8][4][16384];    // Wih  [dir][hl][nblk][kc]
__device__ unsigned char g_fc1Bsw[2][4][8][16384];      // fc1_w [hl][nblk][kc]
__device__ float g_bsum[2][G4H];                        // permuted bih+bhh

__device__ __forceinline__ float sigmoidf_(float x) { return 1.0f / (1.0f + expf(-x)); }
__device__ __forceinline__ float leakyf_(float x)   { return x > 0.0f ? x : 0.01f * x; }
__device__ __forceinline__ uint32_t swz128(uint32_t off) { return off ^ ((off >> 3) & 0x70); }
__device__ __forceinline__ uint32_t smem_u32(const void* p) {
    uint32_t a;
    asm("{ .reg .u64 t; cvta.to.shared.u64 t, %1; cvt.u32.u64 %0, t; }" : "=r"(a) : "l"(p));
    return a;
}
__device__ __forceinline__ void ldsm4(uint32_t* r, uint32_t addr) {
    asm volatile("ldmatrix.sync.aligned.m8n8.x4.shared.b16 {%0,%1,%2,%3}, [%4];"
        : "=r"(r[0]), "=r"(r[1]), "=r"(r[2]), "=r"(r[3]) : "r"(addr));
}
__device__ __forceinline__ void mma_f16(float* d, const uint32_t* a, const uint32_t* b) {
    asm volatile("mma.sync.aligned.m16n8k16.row.col.f32.f16.f16.f32 "
        "{%0,%1,%2,%3}, {%4,%5,%6,%7}, {%8,%9}, {%0,%1,%2,%3};"
        : "+f"(d[0]), "+f"(d[1]), "+f"(d[2]), "+f"(d[3])
        : "r"(a[0]), "r"(a[1]), "r"(a[2]), "r"(a[3]), "r"(b[0]), "r"(b[1]));
}
__device__ __forceinline__ void cpasync16(uint32_t dst, const void* src) {
    asm volatile("cp.async.cg.shared.global [%0], [%1], 16;" :: "r"(dst), "l"(src));
}
#define CPASYNC_COMMIT() asm volatile("cp.async.commit_group;" ::: "memory")
#define CPASYNC_WAIT_ALL() asm volatile("cp.async.wait_group 0;" ::: "memory")

__device__ __forceinline__ uint32_t packh(__half a, __half b) {
    unsigned short ua = *(unsigned short*)&a, ub = *(unsigned short*)&b;
    return (uint32_t)ua | ((uint32_t)ub << 16);
}

#define PV_SMEM  (1024 + 49152 + 512)
#define SB_SMEM  (1024 + 65536 + 512)   /* 48KB stage + 64KB Acc reuse + bias */

// ---------------------------------------------------------------------------
// prep_all: blocks [0,256) Whh split (+bias), [256,512) Wih split,
//           [512,640) fc1_w split. fp16 hi/lo. Permutation p = unit*4+gate.
// ---------------------------------------------------------------------------
__global__ void __launch_bounds__(256) prep_all(const float* __restrict__ Whf, const float* __restrict__ Whb,
                                                const float* __restrict__ Wif, const float* __restrict__ Wib,
                                                const float* __restrict__ fc1w,
                                                const float* __restrict__ bihf, const float* __restrict__ bhhf,
                                                const float* __restrict__ bihb, const float* __restrict__ bhhb)
{
    const int blk = blockIdx.x;
    const int tid = threadIdx.x;
    if (blk < 512) {
        const int sect = blk >> 8;                       // 0 = Whh, 1 = Wih
        int idx = (blk & 255) * 256 + tid;               // 65536 per section
        int dir = idx >> 15;
        int r = idx & 32767;
        int n = r >> 5;
        int k8 = (r & 31) << 3;
        const float* W = sect ? (dir ? Wib : Wif) : (dir ? Whb : Whf);
        int p = ((n & 255) << 2) | (n >> 8);             // unit*4 + gate
        int nblk = p >> 7, prow = p & 127;
        float4 v0 = *(const float4*)(W + (size_t)n * Hh + k8);
        float4 v1 = *(const float4*)(W + (size_t)n * Hh + k8 + 4);
        float vals[8] = {v0.x, v0.y, v0.z, v0.w, v1.x, v1.y, v1.z, v1.w};
#pragma unroll
        for (int j = 0; j < 8; j++) {
            int k = k8 + j;
            int kc = k >> 6, kb = k & 63;
            uint32_t off = swz128((uint32_t)prow * 128u + (uint32_t)kb * 2u);
            __half hi = __float2half(vals[j]);
            __half lo = __float2half(vals[j] - __half2float(hi));
            if (sect == 0) {
                *(__half*)(&g_Bsw[dir][0][nblk][kc][off]) = hi;
                *(__half*)(&g_Bsw[dir][1][nblk][kc][off]) = lo;
            } else {
                *(__half*)(&g_BswIH[dir][0][nblk][kc][off]) = hi;
                *(__half*)(&g_BswIH[dir][1][nblk][kc][off]) = lo;
            }
        }
        if (sect == 0 && k8 == 0) {
            const float* bi = dir ? bihb : bihf;
            const float* bh = dir ? bhhb : bhhf;
            g_bsum[dir][p] = bi[n] + bh[n];
        }
    } else {
        int idx = (blk - 512) * 256 + tid;               // 32768 threads
        int n = idx >> 6;                                // 0..511
        int k8 = (idx & 63) << 3;
        int nblk = n >> 7, prow = n & 127;
        float4 v0 = *(const float4*)(fc1w + (size_t)n * FHh + k8);
        float4 v1 = *(const float4*)(fc1w + (size_t)n * FHh + k8 + 4);
        float vals[8] = {v0.x, v0.y, v0.z, v0.w, v1.x, v1.y, v1.z, v1.w};
#pragma unroll
        for (int j = 0; j < 8; j++) {
            int k = k8 + j;
            int kc = k >> 6, kb = k & 63;
            uint32_t off = swz128((uint32_t)prow * 128u + (uint32_t)kb * 2u);
            __half hi = __float2half(vals[j]);
            __half lo = __float2half(vals[j] - __half2float(hi));
            *(__half*)(&g_fc1Bsw[0][nblk][kc][off]) = hi;
            *(__half*)(&g_fc1Bsw[1][nblk][kc][off]) = lo;
        }
    }
}

// ---------------------------------------------------------------------------
// pv_mma: PVp[dir] = embed(row0=0) @ Wih^T, permuted cols, fp16 2-term.
// smem: A 16KB | Bh 16KB | Bl 16KB. grid (8 nblk, 63 mtile, 2 dir).
// ---------------------------------------------------------------------------
__global__ void __launch_bounds__(256) pv_mma(const float* __restrict__ embed)
{
    extern __shared__ unsigned char smraw[];
    uint32_t sb0 = smem_u32(smraw);
    uint32_t sb = (sb0 + 1023u) & ~1023u;
    unsigned char* smb = smraw + (sb - sb0);

    const int dir = blockIdx.z;
    const int nblk = blockIdx.x;
    const int m0 = blockIdx.y << 7;
    const int tid = threadIdx.x;
    const int lane = tid & 31, wid = tid >> 5;
    const int wm = wid >> 2, wn = wid & 3;

    float acc[4][4][4];
#pragma unroll
    for (int a = 0; a < 4; a++)
#pragma unroll
        for (int b = 0; b < 4; b++)
#pragma unroll
            for (int c = 0; c < 4; c++) acc[a][b][c] = 0.f;

    const uint32_t aBase = sb, bBaseH = sb + 16384u, bBaseL = sb + 32768u;
    const int arow = (wm << 6) + (lane & 15);
    const int atop = (lane >> 4) << 4;
    const int brow = (wn << 5) + (lane & 7) + ((lane & 16) ? 8 : 0);
    const int btop = (lane & 8) ? 16 : 0;

    for (int kc = 0; kc < 4; kc++) {
        // A: embed rows fp32 -> fp16, swizzled
#pragma unroll
        for (int i = 0; i < 4; i++) {
            int u = tid + (i << 8);
            int r = u >> 3, c8 = u & 7;
            int g = m0 + r;
            float vals[8];
            if (g == 0 || g >= Vv) {
#pragma unroll
                for (int j = 0; j < 8; j++) vals[j] = 0.f;
            } else {
                float4 v0 = *(const float4*)(embed + (size_t)g * Ee + (kc << 6) + (c8 << 3));
                float4 v1 = *(const float4*)(embed + (size_t)g * Ee + (kc << 6) + (c8 << 3) + 4);
                vals[0] = v0.x; vals[1] = v0.y; vals[2] = v0.z; vals[3] = v0.w;
                vals[4] = v1.x; vals[5] = v1.y; vals[6] = v1.z; vals[7] = v1.w;
            }
            uint4 hv;
            hv.x = packh(__float2half(vals[0]), __float2half(vals[1]));
            hv.y = packh(__float2half(vals[2]), __float2half(vals[3]));
            hv.z = packh(__float2half(vals[4]), __float2half(vals[5]));
            hv.w = packh(__float2half(vals[6]), __float2half(vals[7]));
            *(uint4*)(smb + swz128((uint32_t)r * 128u + ((uint32_t)c8 << 4))) = hv;
        }
        // B: pre-swizzled copy (hi, lo)
#pragma unroll
        for (int hl = 0; hl < 2; hl++) {
            const uint4* src = (const uint4*)&g_BswIH[dir][hl][nblk][kc][0];
            uint4* dst = (uint4*)(smb + 16384 + hl * 16384);
#pragma unroll
            for (int i = 0; i < 4; i++) dst[tid + (i << 8)] = src[tid + (i << 8)];
        }
        __syncthreads();

#pragma unroll
        for (int ks = 0; ks < 4; ks++) {
            const uint32_t kbyte = (uint32_t)ks << 5;
            uint32_t ah[4][4], bh[8], bl[8];
#pragma unroll
            for (int mi = 0; mi < 4; mi++) {
                uint32_t off = swz128((uint32_t)(arow + mi * 16) * 128u + kbyte + (uint32_t)atop);
                ldsm4(ah[mi], aBase + off);
            }
#pragma unroll
            for (int bi = 0; bi < 2; bi++) {
                uint32_t off = swz128((uint32_t)(brow + bi * 16) * 128u + kbyte + (uint32_t)btop);
                ldsm4(bh + bi * 4, bBaseH + off);
                ldsm4(bl + bi * 4, bBaseL + off);
            }
#pragma unroll
            for (int mi = 0; mi < 4; mi++)
#pragma unroll
                for (int ni = 0; ni < 4; ni++) {
                    mma_f16(acc[mi][ni], ah[mi], bh + ni * 2);
                    mma_f16(acc[mi][ni], ah[mi], bl + ni * 2);
                }
        }
        __syncthreads();
    }

    float* out = g_PVp[dir];
#pragma unroll
    for (int mi = 0; mi < 4; mi++) {
        int r0 = m0 + (wm << 6) + mi * 16 + (lane >> 2);
#pragma unroll
        for (int ni = 0; ni < 4; ni++) {
            int c0 = (nblk << 7) + (wn << 5) + ni * 8 + ((lane & 3) << 1);
            if (r0 < Vv)
                *(float2*)(out + (size_t)r0 * G4H + c0) = make_float2(acc[mi][ni][0], acc[mi][ni][1]);
            if (r0 + 8 < Vv)
                *(float2*)(out + (size_t)(r0 + 8) * G4H + c0) = make_float2(acc[mi][ni][2], acc[mi][ni][3]);
        }
    }
}

// ---------------------------------------------------------------------------
// zero h (buf0, both dirs, fp16) and c (both dirs, fp32)
// ---------------------------------------------------------------------------
__global__ void __launch_bounds__(256) zero_state()
{
    const int i = blockIdx.x * 256 + threadIdx.x;        // 3,145,728 uint4 total
    const uint4 z = make_uint4(0u, 0u, 0u, 0u);
    if (i < 1048576) {
        int dir = i >> 19;                               // 524288 uint4 per fp16 plane
        ((uint4*)g_hA[dir][0])[i & 524287] = z;
    } else {
        int j = i - 1048576;                             // 1,048,576 uint4 per c slice
        int dir = j >> 20;
        ((uint4*)g_cst[dir])[j & 1048575] = z;
    }
}

// ---------------------------------------------------------------------------
// gates_mma: one LSTM step, both dirs. fp16 2-term (A=h fp16, B=Whh hi/lo).
// Single 48KB stage, cp.async, 2 CTAs/SM; fused LSTM epilogue.
// ---------------------------------------------------------------------------
__global__ void __launch_bounds__(256, 2) gates_mma(const int* __restrict__ x, int step)
{
    extern __shared__ unsigned char smraw[];
    uint32_t sb0 = smem_u32(smraw);
    uint32_t sb = (sb0 + 1023u) & ~1023u;
    unsigned char* smb = smraw + (sb - sb0);

    const int dir = blockIdx.z;
    const int nblk = blockIdx.x;
    const int m0 = blockIdx.y << 7;
    const int tid = threadIdx.x;
    const int lane = tid & 31, wid = tid >> 5;
    const int wm = wid >> 2, wn = wid & 3;
    const int buf = step & 1, nbuf = buf ^ 1;

    float* biasf = (float*)(smb + 65536);
    if (tid < 32)
        *(float4*)(biasf + (tid << 2)) = *(const float4*)(g_bsum[dir] + (nblk << 7) + (tid << 2));

    const uint4* srcA = (const uint4*)g_hA[dir][buf];

    float acc[4][4][4];
#pragma unroll
    for (int a = 0; a < 4; a++)
#pragma unroll
        for (int b = 0; b < 4; b++)
#pragma unroll
            for (int c = 0; c < 4; c++) acc[a][b][c] = 0.f;

    const int arow = (wm << 6) + (lane & 15);
    const int atop = (lane >> 4) << 4;
    const int brow = (wn << 5) + (lane & 7) + ((lane & 16) ? 8 : 0);
    const int btop = (lane & 8) ? 16 : 0;

    for (int kc = 0; kc < 4; kc++) {
        // A: single fp16 plane, 16KB
#pragma unroll
        for (int i = 0; i < 4; i++) {
            int u = tid + (i << 8);
            int r = u >> 3, c16 = u & 7;
            uint32_t dst = sb + swz128((uint32_t)r * 128u + ((uint32_t)c16 << 4));
            cpasync16(dst, &srcA[(size_t)(m0 + r) * 32 + (kc << 3) + c16]);
        }
        // B hi/lo, 16KB each
#pragma unroll
        for (int hl = 0; hl < 2; hl++) {
            const unsigned char* src = &g_Bsw[dir][hl][nblk][kc][0];
#pragma unroll
            for (int i = 0; i < 4; i++) {
                uint32_t o = ((uint32_t)tid + ((uint32_t)i << 8)) << 4;
                cpasync16(sb + 16384u + (uint32_t)hl * 16384u + o, src + o);
            }
        }
        CPASYNC_COMMIT();
        CPASYNC_WAIT_ALL();
        __syncthreads();

        const uint32_t aB = sb, bH = sb + 16384u, bL = sb + 32768u;
#pragma unroll
        for (int ks = 0; ks < 4; ks++) {
            const uint32_t kbyte = (uint32_t)ks << 5;
            uint32_t ah[4][4], bh[8], bl[8];
#pragma unroll
            for (int mi = 0; mi < 4; mi++) {
                uint32_t off = swz128((uint32_t)(arow + mi * 16) * 128u + kbyte + (uint32_t)atop);
                ldsm4(ah[mi], aB + off);
            }
#pragma unroll
            for (int bi = 0; bi < 2; bi++) {
                uint32_t off = swz128((uint32_t)(brow + bi * 16) * 128u + kbyte + (uint32_t)btop);
                ldsm4(bh + bi * 4, bH + off);
                ldsm4(bl + bi * 4, bL + off);
            }
#pragma unroll
            for (int mi = 0; mi < 4; mi++)
#pragma unroll
                for (int ni = 0; ni < 4; ni++) {
                    mma_f16(acc[mi][ni], ah[mi], bh + ni * 2);
                    mma_f16(acc[mi][ni], ah[mi], bl + ni * 2);
                }
        }
        __syncthreads();
    }

    // stage accumulators into smem (reuse tile region; safe after final sync)
    float* Acc = (float*)smb;
#pragma unroll
    for (int mi = 0; mi < 4; mi++)
#pragma unroll
        for (int ni = 0; ni < 4; ni++) {
            int r0 = (wm << 6) + mi * 16 + (lane >> 2);
            int c0 = (wn << 5) + ni * 8 + ((lane & 3) << 1);
            *(float2*)(Acc + r0 * 128 + c0) = make_float2(acc[mi][ni][0], acc[mi][ni][1]);
            *(float2*)(Acc + (r0 + 8) * 128 + c0) = make_float2(acc[mi][ni][2], acc[mi][ni][3]);
        }
    __syncthreads();

    // fused epilogue: 2 threads per row, 16 units each
    const int row_l = tid >> 1;
    const int half = tid & 1;
    const int row = m0 + row_l;
    const int t = row & (Ss - 1), bidx = row >> 10;
    const int tp = dir ? (t + WSw - step) : (t - WSw + step);
    const bool valid = ((unsigned)tp < (unsigned)Ss);
    const int tok = valid ? x[(bidx << 10) + tp] : 0;
    const bool finalstep = (step == WSw);

    const float4* accu = (const float4*)(Acc + row_l * 128 + (half << 6));
    const float4* bsu  = (const float4*)(biasf + (half << 6));
    const float4* pvu  = (const float4*)(g_PVp[dir] + (size_t)tok * G4H + (nblk << 7) + (half << 6));
    float4* cp = (float4*)(g_cst[dir] + (size_t)row * Hh + (nblk << 5) + (half << 4));
    const int colbase = (nblk << 5) + (half << 4);
    __half* hip = g_hA[dir][nbuf] + (size_t)row * Hh + colbase;
    __half* fHp = g_fcA + (size_t)row * FHh + dir * Hh + colbase;

    uint32_t hwH[8], fwH[8];
#pragma unroll
    for (int g4 = 0; g4 < 4; g4++) {
        float4 cv = cp[g4];
        float cin[4] = {cv.x, cv.y, cv.z, cv.w};
        float ho[4];
#pragma unroll
        for (int j = 0; j < 4; j++) {
            int u = g4 * 4 + j;
            float4 gq = accu[u];
            float4 bq = bsu[u];
            float pi = gq.x + bq.x, pf = gq.y + bq.y, pg = gq.z + bq.z, po = gq.w + bq.w;
            if (valid) {
                float4 pq = pvu[u];
                pi += pq.x; pf += pq.y; pg += pq.z; po += pq.w;
            }
            float iv = sigmoidf_(pi), fv = sigmoidf_(pf), gv = tanhf(pg), ov = sigmoidf_(po);
            float cn = fv * cin[j] + iv * gv;
            cin[j] = cn;
            ho[j] = ov * tanhf(cn);
        }
        cp[g4] = make_float4(cin[0], cin[1], cin[2], cin[3]);
        hwH[g4 * 2 + 0] = packh(__float2half(ho[0]), __float2half(ho[1]));
        hwH[g4 * 2 + 1] = packh(__float2half(ho[2]), __float2half(ho[3]));
        if (finalstep) {
            fwH[g4 * 2 + 0] = packh(__float2half(leakyf_(ho[0])), __float2half(leakyf_(ho[1])));
            fwH[g4 * 2 + 1] = packh(__float2half(leakyf_(ho[2])), __float2half(leakyf_(ho[3])));
        }
    }
    *(uint4*)hip       = make_uint4(hwH[0], hwH[1], hwH[2], hwH[3]);
    *(uint4*)(hip + 8) = make_uint4(hwH[4], hwH[5], hwH[6], hwH[7]);
    if (finalstep) {
        *(uint4*)fHp       = make_uint4(fwH[0], fwH[1], fwH[2], fwH[3]);
        *(uint4*)(fHp + 8) = make_uint4(fwH[4], fwH[5], fwH[6], fwH[7]);
    }
}

// ---------------------------------------------------------------------------
// fc1_mma: g_fc1 = leaky( fcA @ fc1_w^T + fc1_b ). fp16 2-term, 2 CTAs/SM.
// grid (4 nblk, 128 mtile), 256 thr. K=512 in 8 chunks.
// ---------------------------------------------------------------------------
__global__ void __launch_bounds__(256, 2) fc1_mma(const float* __restrict__ fc1_b)
{
    extern __shared__ unsigned char smraw[];
    uint32_t sb0 = smem_u32(smraw);
    uint32_t sb = (sb0 + 1023u) & ~1023u;
    unsigned char* smb = smraw + (sb - sb0);

    const int nblk = blockIdx.x;
    const int m0 = blockIdx.y << 7;
    const int tid = threadIdx.x;
    const int lane = tid & 31, wid = tid >> 5;
    const int wm = wid >> 2, wn = wid & 3;

    float* biasf = (float*)(smb + 65536);
    if (tid < 32)
        *(float4*)(biasf + (tid << 2)) = *(const float4*)(fc1_b + (nblk << 7) + (tid << 2));

    float acc[4][4][4];
#pragma unroll
    for (int a = 0; a < 4; a++)
#pragma unroll
        for (int b = 0; b < 4; b++)
#pragma unroll
            for (int c = 0; c < 4; c++) acc[a][b][c] = 0.f;

    const int arow = (wm << 6) + (lane & 15);
    const int atop = (lane >> 4) << 4;
    const int brow = (wn << 5) + (lane & 7) + ((lane & 16) ? 8 : 0);
    const int btop = (lane & 8) ? 16 : 0;

    for (int kc = 0; kc < 8; kc++) {
        const uint4* srcA = (const uint4*)g_fcA;
#pragma unroll
        for (int i = 0; i < 4; i++) {
            int u = tid + (i << 8);
            int r = u >> 3, c16 = u & 7;
            uint32_t dst = sb + swz128((uint32_t)r * 128u + ((uint32_t)c16 << 4));
            cpasync16(dst, &srcA[(size_t)(m0 + r) * 64 + (kc << 3) + c16]);
        }
#pragma unroll
        for (int hl = 0; hl < 2; hl++) {
            const unsigned char* src = &g_fc1Bsw[hl][nblk][kc][0];
#pragma unroll
            for (int i = 0; i < 4; i++) {
                uint32_t o = ((uint32_t)tid + ((uint32_t)i << 8)) << 4;
                cpasync16(sb + 16384u + (uint32_t)hl * 16384u + o, src + o);
            }
        }
        CPASYNC_COMMIT();
        CPASYNC_WAIT_ALL();
        __syncthreads();

        const uint32_t aB = sb, bH = sb + 16384u, bL = sb + 32768u;
#pragma unroll
        for (int ks = 0; ks < 4; ks++) {
            const uint32_t kbyte = (uint32_t)ks << 5;
            uint32_t ah[4][4], bh[8], bl[8];
#pragma unroll
            for (int mi = 0; mi < 4; mi++) {
                uint32_t off = swz128((uint32_t)(arow + mi * 16) * 128u + kbyte + (uint32_t)atop);
                ldsm4(ah[mi], aB + off);
            }
#pragma unroll
            for (int bi = 0; bi < 2; bi++) {
                uint32_t off = swz128((uint32_t)(brow + bi * 16) * 128u + kbyte + (uint32_t)btop);
                ldsm4(bh + bi * 4, bH + off);
                ldsm4(bl + bi * 4, bL + off);
            }
#pragma unroll
            for (int mi = 0; mi < 4; mi++)
#pragma unroll
                for (int ni = 0; ni < 4; ni++) {
                    mma_f16(acc[mi][ni], ah[mi], bh + ni * 2);
                    mma_f16(acc[mi][ni], ah[mi], bl + ni * 2);
                }
        }
        __syncthreads();
    }

    // epilogue: bias + leaky, direct register store
#pragma unroll
    for (int mi = 0; mi < 4; mi++) {
        int r0 = m0 + (wm << 6) + mi * 16 + (lane >> 2);
#pragma unroll
        for (int ni = 0; ni < 4; ni++) {
            int cl = (wn << 5) + ni * 8 + ((lane & 3) << 1);
            int c0 = (nblk << 7) + cl;
            float b0 = biasf[cl], b1 = biasf[cl + 1];
            *(float2*)(g_fc1 + (size_t)r0 * FHh + c0) =
                make_float2(leakyf_(acc[mi][ni][0] + b0), leakyf_(acc[mi][ni][1] + b1));
            *(float2*)(g_fc1 + (size_t)(r0 + 8) * FHh + c0) =
                make_float2(leakyf_(acc[mi][ni][2] + b0), leakyf_(acc[mi][ni][3] + b1));
        }
    }
}

// ---------------------------------------------------------------------------
// fc2: out[n] = sigmoid( g_fc1[n] . fc2_w + fc2_b )
// ---------------------------------------------------------------------------
__global__ void __launch_bounds__(128) fc2_kernel(const float* __restrict__ w,
                                                  const float* __restrict__ b,
                                                  float* __restrict__ out)
{
    const int n = blockIdx.x;
    const int t = threadIdx.x;
    const float4 a = ((const float4*)(g_fc1 + (size_t)n * FHh))[t];
    const float4 wv = ((const float4*)w)[t];
    float s = a.x * wv.x + a.y * wv.y + a.z * wv.z + a.w * wv.w;
#pragma unroll
    for (int o = 16; o > 0; o >>= 1) s += __shfl_xor_sync(0xffffffffu, s, o);
    __shared__ float ws[4];
    if ((t & 31) == 0) ws[t >> 5] = s;
    __syncthreads();
    if (t == 0) {
        const float tot = ws[0] + ws[1] + ws[2] + ws[3];
        out[n] = 1.0f / (1.0f + expf(-(tot + b[0])));
    }
}

// ---------------------------------------------------------------------------
extern "C" void kernel_launch(void* const* d_in, const int* in_sizes, int n_in,
                              void* d_out, int out_size)
{
    const int*   x      = (const int*)  d_in[0];
    const float* embed  = (const float*)d_in[1];
    const float* Wih_f  = (const float*)d_in[2];
    const float* Whh_f  = (const float*)d_in[3];
    const float* bih_f  = (const float*)d_in[4];
    const float* bhh_f  = (const float*)d_in[5];
    const float* Wih_b  = (const float*)d_in[6];
    const float* Whh_b  = (const float*)d_in[7];
    const float* bih_b  = (const float*)d_in[8];
    const float* bhh_b  = (const float*)d_in[9];
    const float* fc1_w  = (const float*)d_in[10];
    const float* fc1_b  = (const float*)d_in[11];
    const float* fc2_w  = (const float*)d_in[12];
    const float* fc2_b  = (const float*)d_in[13];
    float* out = (float*)d_out;

    cudaFuncSetAttribute(gates_mma, cudaFuncAttributeMaxDynamicSharedMemorySize, SB_SMEM);
    cudaFuncSetAttribute(fc1_mma,   cudaFuncAttributeMaxDynamicSharedMemorySize, SB_SMEM);
    cudaFuncSetAttribute(pv_mma,    cudaFuncAttributeMaxDynamicSharedMemorySize, PV_SMEM);

    prep_all<<<640, 256>>>(Whh_f, Whh_b, Wih_f, Wih_b, fc1_w,
                           bih_f, bhh_f, bih_b, bhh_b);
    pv_mma<<<dim3(8, 63, 2), 256, PV_SMEM>>>(embed);
    zero_state<<<12288, 256>>>();

    for (int k = 0; k <= WSw; k++) {
        gates_mma<<<dim3(8, NTOK / 128, 2), 256, SB_SMEM>>>(x, k);
    }

    fc1_mma<<<dim3(4, 128), 256, SB_SMEM>>>(fc1_b);
    fc2_kernel<<<NTOK, 128>>>(fc2_w, fc2_b, out);
}

// round 12
// speedup vs baseline: 2.2642x; 1.4096x over previous
#include <cuda_runtime.h>
#include <cuda_fp16.h>
#include <math.h>
#include <stdint.h>

#define Bb   16
#define Ss   1024
#define Ee   256
#define Hh   256
#define FHh  512
#define Vv   8000
#define WSw  5
#define NTOK (Bb*Ss)     /* 16384 */
#define G4H  (4*Hh)      /* 1024  */

// ---------------- scratch (device globals; no dynamic allocation) ----------
__device__ float g_PVp[2][(size_t)Vv * G4H];            // permuted-col input projections
__device__ __half g_hA[2][2][(size_t)NTOK * Hh];        // [dir][pingpong] h as fp16
__device__ float g_cst[2][(size_t)NTOK * Hh];           // [dir] c state
__device__ __half g_fcA[(size_t)NTOK * FHh];            // leaky(h) concat, fc1 A (fp16)
__device__ float g_fc1[(size_t)NTOK * FHh];
// fp16 weights, col-permuted, pre-swizzled tiles (128 rows x 64 k = 16KB)
__device__ unsigned char g_Bsw[2][8][4][16384];         // Whh  [dir][nblk][kc]
__device__ unsigned char g_BswIH[2][8][4][16384];       // Wih  [dir][nblk][kc]
__device__ unsigned char g_fc1Bsw[4][8][16384];         // fc1_w [nblk][kc]
__device__ float g_bsum[2][G4H];                        // permuted bih+bhh

__device__ __forceinline__ float sigmoidf_(float x) { return 1.0f / (1.0f + expf(-x)); }
__device__ __forceinline__ float leakyf_(float x)   { return x > 0.0f ? x : 0.01f * x; }
__device__ __forceinline__ uint32_t swz128(uint32_t off) { return off ^ ((off >> 3) & 0x70); }
__device__ __forceinline__ uint32_t smem_u32(const void* p) {
    uint32_t a;
    asm("{ .reg .u64 t; cvta.to.shared.u64 t, %1; cvt.u32.u64 %0, t; }" : "=r"(a) : "l"(p));
    return a;
}
__device__ __forceinline__ void ldsm4(uint32_t* r, uint32_t addr) {
    asm volatile("ldmatrix.sync.aligned.m8n8.x4.shared.b16 {%0,%1,%2,%3}, [%4];"
        : "=r"(r[0]), "=r"(r[1]), "=r"(r[2]), "=r"(r[3]) : "r"(addr));
}
__device__ __forceinline__ void mma_f16(float* d, const uint32_t* a, const uint32_t* b) {
    asm volatile("mma.sync.aligned.m16n8k16.row.col.f32.f16.f16.f32 "
        "{%0,%1,%2,%3}, {%4,%5,%6,%7}, {%8,%9}, {%0,%1,%2,%3};"
        : "+f"(d[0]), "+f"(d[1]), "+f"(d[2]), "+f"(d[3])
        : "r"(a[0]), "r"(a[1]), "r"(a[2]), "r"(a[3]), "r"(b[0]), "r"(b[1]));
}
__device__ __forceinline__ void cpasync16(uint32_t dst, const void* src) {
    asm volatile("cp.async.cg.shared.global [%0], [%1], 16;" :: "r"(dst), "l"(src));
}
#define CPASYNC_COMMIT() asm volatile("cp.async.commit_group;" ::: "memory")
#define CPASYNC_WAIT_ALL() asm volatile("cp.async.wait_group 0;" ::: "memory")

__device__ __forceinline__ uint32_t packh(__half a, __half b) {
    unsigned short ua = *(unsigned short*)&a, ub = *(unsigned short*)&b;
    return (uint32_t)ua | ((uint32_t)ub << 16);
}

#define PV_SMEM  (1024 + 32768 + 512)
#define SB_SMEM  (1024 + 65536 + 512)   /* 32KB stage; 64KB Acc reuse; bias */

// ---------------------------------------------------------------------------
// prep_all: blocks [0,256) Whh (+bias), [256,512) Wih, [512,640) fc1_w.
// fp16 RN, permutation p = unit*4+gate for Whh/Wih, pre-swizzled.
// ---------------------------------------------------------------------------
__global__ void __launch_bounds__(256) prep_all(const float* __restrict__ Whf, const float* __restrict__ Whb,
                                                const float* __restrict__ Wif, const float* __restrict__ Wib,
                                                const float* __restrict__ fc1w,
                                                const float* __restrict__ bihf, const float* __restrict__ bhhf,
                                                const float* __restrict__ bihb, const float* __restrict__ bhhb)
{
    const int blk = blockIdx.x;
    const int tid = threadIdx.x;
    if (blk < 512) {
        const int sect = blk >> 8;                       // 0 = Whh, 1 = Wih
        int idx = (blk & 255) * 256 + tid;               // 65536 per section
        int dir = idx >> 15;
        int r = idx & 32767;
        int n = r >> 5;
        int k8 = (r & 31) << 3;
        const float* W = sect ? (dir ? Wib : Wif) : (dir ? Whb : Whf);
        int p = ((n & 255) << 2) | (n >> 8);             // unit*4 + gate
        int nblk = p >> 7, prow = p & 127;
        float4 v0 = *(const float4*)(W + (size_t)n * Hh + k8);
        float4 v1 = *(const float4*)(W + (size_t)n * Hh + k8 + 4);
        float vals[8] = {v0.x, v0.y, v0.z, v0.w, v1.x, v1.y, v1.z, v1.w};
#pragma unroll
        for (int j = 0; j < 8; j++) {
            int k = k8 + j;
            int kc = k >> 6, kb = k & 63;
            uint32_t off = swz128((uint32_t)prow * 128u + (uint32_t)kb * 2u);
            __half hv = __float2half(vals[j]);
            if (sect == 0) *(__half*)(&g_Bsw[dir][nblk][kc][off]) = hv;
            else           *(__half*)(&g_BswIH[dir][nblk][kc][off]) = hv;
        }
        if (sect == 0 && k8 == 0) {
            const float* bi = dir ? bihb : bihf;
            const float* bh = dir ? bhhb : bhhf;
            g_bsum[dir][p] = bi[n] + bh[n];
        }
    } else {
        int idx = (blk - 512) * 256 + tid;               // 32768 threads
        int n = idx >> 6;                                // 0..511
        int k8 = (idx & 63) << 3;
        int nblk = n >> 7, prow = n & 127;
        float4 v0 = *(const float4*)(fc1w + (size_t)n * FHh + k8);
        float4 v1 = *(const float4*)(fc1w + (size_t)n * FHh + k8 + 4);
        float vals[8] = {v0.x, v0.y, v0.z, v0.w, v1.x, v1.y, v1.z, v1.w};
#pragma unroll
        for (int j = 0; j < 8; j++) {
            int k = k8 + j;
            int kc = k >> 6, kb = k & 63;
            uint32_t off = swz128((uint32_t)prow * 128u + (uint32_t)kb * 2u);
            *(__half*)(&g_fc1Bsw[nblk][kc][off]) = __float2half(vals[j]);
        }
    }
}

// ---------------------------------------------------------------------------
// pv_mma: PVp[dir] = embed(row0=0) @ Wih^T, permuted cols, fp16 1-term.
// smem: A 16KB | B 16KB. grid (8 nblk, 63 mtile, 2 dir).
// ---------------------------------------------------------------------------
__global__ void __launch_bounds__(256) pv_mma(const float* __restrict__ embed)
{
    extern __shared__ unsigned char smraw[];
    uint32_t sb0 = smem_u32(smraw);
    uint32_t sb = (sb0 + 1023u) & ~1023u;
    unsigned char* smb = smraw + (sb - sb0);

    const int dir = blockIdx.z;
    const int nblk = blockIdx.x;
    const int m0 = blockIdx.y << 7;
    const int tid = threadIdx.x;
    const int lane = tid & 31, wid = tid >> 5;
    const int wm = wid >> 2, wn = wid & 3;

    float acc[4][4][4];
#pragma unroll
    for (int a = 0; a < 4; a++)
#pragma unroll
        for (int b = 0; b < 4; b++)
#pragma unroll
            for (int c = 0; c < 4; c++) acc[a][b][c] = 0.f;

    const uint32_t aBase = sb, bBase = sb + 16384u;
    const int arow = (wm << 6) + (lane & 15);
    const int atop = (lane >> 4) << 4;
    const int brow = (wn << 5) + (lane & 7) + ((lane & 16) ? 8 : 0);
    const int btop = (lane & 8) ? 16 : 0;

    for (int kc = 0; kc < 4; kc++) {
#pragma unroll
        for (int i = 0; i < 4; i++) {
            int u = tid + (i << 8);
            int r = u >> 3, c8 = u & 7;
            int g = m0 + r;
            float vals[8];
            if (g == 0 || g >= Vv) {
#pragma unroll
                for (int j = 0; j < 8; j++) vals[j] = 0.f;
            } else {
                float4 v0 = *(const float4*)(embed + (size_t)g * Ee + (kc << 6) + (c8 << 3));
                float4 v1 = *(const float4*)(embed + (size_t)g * Ee + (kc << 6) + (c8 << 3) + 4);
                vals[0] = v0.x; vals[1] = v0.y; vals[2] = v0.z; vals[3] = v0.w;
                vals[4] = v1.x; vals[5] = v1.y; vals[6] = v1.z; vals[7] = v1.w;
            }
            uint4 hv;
            hv.x = packh(__float2half(vals[0]), __float2half(vals[1]));
            hv.y = packh(__float2half(vals[2]), __float2half(vals[3]));
            hv.z = packh(__float2half(vals[4]), __float2half(vals[5]));
            hv.w = packh(__float2half(vals[6]), __float2half(vals[7]));
            *(uint4*)(smb + swz128((uint32_t)r * 128u + ((uint32_t)c8 << 4))) = hv;
        }
        {
            const uint4* src = (const uint4*)&g_BswIH[dir][nblk][kc][0];
            uint4* dst = (uint4*)(smb + 16384);
#pragma unroll
            for (int i = 0; i < 4; i++) dst[tid + (i << 8)] = src[tid + (i << 8)];
        }
        __syncthreads();

#pragma unroll
        for (int ks = 0; ks < 4; ks++) {
            const uint32_t kbyte = (uint32_t)ks << 5;
            uint32_t ah[4][4], bh[8];
#pragma unroll
            for (int mi = 0; mi < 4; mi++) {
                uint32_t off = swz128((uint32_t)(arow + mi * 16) * 128u + kbyte + (uint32_t)atop);
                ldsm4(ah[mi], aBase + off);
            }
#pragma unroll
            for (int bi = 0; bi < 2; bi++) {
                uint32_t off = swz128((uint32_t)(brow + bi * 16) * 128u + kbyte + (uint32_t)btop);
                ldsm4(bh + bi * 4, bBase + off);
            }
#pragma unroll
            for (int mi = 0; mi < 4; mi++)
#pragma unroll
                for (int ni = 0; ni < 4; ni++)
                    mma_f16(acc[mi][ni], ah[mi], bh + ni * 2);
        }
        __syncthreads();
    }

    float* out = g_PVp[dir];
#pragma unroll
    for (int mi = 0; mi < 4; mi++) {
        int r0 = m0 + (wm << 6) + mi * 16 + (lane >> 2);
#pragma unroll
        for (int ni = 0; ni < 4; ni++) {
            int c0 = (nblk << 7) + (wn << 5) + ni * 8 + ((lane & 3) << 1);
            if (r0 < Vv)
                *(float2*)(out + (size_t)r0 * G4H + c0) = make_float2(acc[mi][ni][0], acc[mi][ni][1]);
            if (r0 + 8 < Vv)
                *(float2*)(out + (size_t)(r0 + 8) * G4H + c0) = make_float2(acc[mi][ni][2], acc[mi][ni][3]);
        }
    }
}

// ---------------------------------------------------------------------------
// gates_init: step 0 exactly (h0 = c0 = 0): gates = PV[tok] + bias;
// c1 = sig(i)*tanh(g); h1 = sig(o)*tanh(c1). Writes c and h buffer 1.
// One thread = 8 units of one (row, dir).
// ---------------------------------------------------------------------------
__global__ void __launch_bounds__(256) gates_init(const int* __restrict__ x)
{
    int idx = blockIdx.x * 256 + threadIdx.x;          // 2 * 16384 * 32
    int dir = idx >> 19;
    int r = idx & 524287;
    int row = r >> 5;
    int u8 = (r & 31) << 3;                            // unit base (8 units)
    int t = row & (Ss - 1), bidx = row >> 10;
    int tp = dir ? (t + WSw) : (t - WSw);
    bool valid = ((unsigned)tp < (unsigned)Ss);
    int tok = valid ? x[(bidx << 10) + tp] : 0;
    const float* pv = g_PVp[dir] + (size_t)tok * G4H + (u8 << 2);
    const float* bs = g_bsum[dir] + (u8 << 2);
    float* crow = g_cst[dir] + (size_t)row * Hh + u8;
    __half* hrow = g_hA[dir][1] + (size_t)row * Hh + u8;

    float c8[8];
    uint32_t hw[4];
#pragma unroll
    for (int j = 0; j < 8; j += 2) {
        float g0[4], g1[4];
#pragma unroll
        for (int q = 0; q < 4; q++) {
            g0[q] = bs[j * 4 + q];
            g1[q] = bs[j * 4 + 4 + q];
        }
        if (valid) {
            float4 p0 = *(const float4*)(pv + j * 4);
            float4 p1 = *(const float4*)(pv + j * 4 + 4);
            g0[0] += p0.x; g0[1] += p0.y; g0[2] += p0.z; g0[3] += p0.w;
            g1[0] += p1.x; g1[1] += p1.y; g1[2] += p1.z; g1[3] += p1.w;
        }
        float cn0 = sigmoidf_(g0[0]) * tanhf(g0[2]);
        float cn1 = sigmoidf_(g1[0]) * tanhf(g1[2]);
        float h0 = sigmoidf_(g0[3]) * tanhf(cn0);
        float h1 = sigmoidf_(g1[3]) * tanhf(cn1);
        c8[j] = cn0; c8[j + 1] = cn1;
        hw[j >> 1] = packh(__float2half(h0), __float2half(h1));
    }
    *(float4*)crow       = make_float4(c8[0], c8[1], c8[2], c8[3]);
    *(float4*)(crow + 4) = make_float4(c8[4], c8[5], c8[6], c8[7]);
    *(uint4*)hrow = make_uint4(hw[0], hw[1], hw[2], hw[3]);
}

// ---------------------------------------------------------------------------
// gates_mma: one LSTM step (steps 1..5), both dirs. fp16 1-term.
// 32KB stage, cp.async, 2 CTAs/SM; fused LSTM epilogue.
// ---------------------------------------------------------------------------
__global__ void __launch_bounds__(256, 2) gates_mma(const int* __restrict__ x, int step)
{
    extern __shared__ unsigned char smraw[];
    uint32_t sb0 = smem_u32(smraw);
    uint32_t sb = (sb0 + 1023u) & ~1023u;
    unsigned char* smb = smraw + (sb - sb0);

    const int dir = blockIdx.z;
    const int nblk = blockIdx.x;
    const int m0 = blockIdx.y << 7;
    const int tid = threadIdx.x;
    const int lane = tid & 31, wid = tid >> 5;
    const int wm = wid >> 2, wn = wid & 3;
    const int buf = step & 1, nbuf = buf ^ 1;

    float* biasf = (float*)(smb + 65536);
    if (tid < 32)
        *(float4*)(biasf + (tid << 2)) = *(const float4*)(g_bsum[dir] + (nblk << 7) + (tid << 2));

    const uint4* srcA = (const uint4*)g_hA[dir][buf];

    float acc[4][4][4];
#pragma unroll
    for (int a = 0; a < 4; a++)
#pragma unroll
        for (int b = 0; b < 4; b++)
#pragma unroll
            for (int c = 0; c < 4; c++) acc[a][b][c] = 0.f;

    const int arow = (wm << 6) + (lane & 15);
    const int atop = (lane >> 4) << 4;
    const int brow = (wn << 5) + (lane & 7) + ((lane & 16) ? 8 : 0);
    const int btop = (lane & 8) ? 16 : 0;

    for (int kc = 0; kc < 4; kc++) {
        // A: fp16 plane, 16KB
#pragma unroll
        for (int i = 0; i < 4; i++) {
            int u = tid + (i << 8);
            int r = u >> 3, c16 = u & 7;
            uint32_t dst = sb + swz128((uint32_t)r * 128u + ((uint32_t)c16 << 4));
            cpasync16(dst, &srcA[(size_t)(m0 + r) * 32 + (kc << 3) + c16]);
        }
        // B: 16KB
        {
            const unsigned char* src = &g_Bsw[dir][nblk][kc][0];
#pragma unroll
            for (int i = 0; i < 4; i++) {
                uint32_t o = ((uint32_t)tid + ((uint32_t)i << 8)) << 4;
                cpasync16(sb + 16384u + o, src + o);
            }
        }
        CPASYNC_COMMIT();
        CPASYNC_WAIT_ALL();
        __syncthreads();

        const uint32_t aB = sb, bB = sb + 16384u;
#pragma unroll
        for (int ks = 0; ks < 4; ks++) {
            const uint32_t kbyte = (uint32_t)ks << 5;
            uint32_t ah[4][4], bh[8];
#pragma unroll
            for (int mi = 0; mi < 4; mi++) {
                uint32_t off = swz128((uint32_t)(arow + mi * 16) * 128u + kbyte + (uint32_t)atop);
                ldsm4(ah[mi], aB + off);
            }
#pragma unroll
            for (int bi = 0; bi < 2; bi++) {
                uint32_t off = swz128((uint32_t)(brow + bi * 16) * 128u + kbyte + (uint32_t)btop);
                ldsm4(bh + bi * 4, bB + off);
            }
#pragma unroll
            for (int mi = 0; mi < 4; mi++)
#pragma unroll
                for (int ni = 0; ni < 4; ni++)
                    mma_f16(acc[mi][ni], ah[mi], bh + ni * 2);
        }
        __syncthreads();
    }

    // stage accumulators into smem (reuse tile region; safe after final sync)
    float* Acc = (float*)smb;
#pragma unroll
    for (int mi = 0; mi < 4; mi++)
#pragma unroll
        for (int ni = 0; ni < 4; ni++) {
            int r0 = (wm << 6) + mi * 16 + (lane >> 2);
            int c0 = (wn << 5) + ni * 8 + ((lane & 3) << 1);
            *(float2*)(Acc + r0 * 128 + c0) = make_float2(acc[mi][ni][0], acc[mi][ni][1]);
            *(float2*)(Acc + (r0 + 8) * 128 + c0) = make_float2(acc[mi][ni][2], acc[mi][ni][3]);
        }
    __syncthreads();

    // fused epilogue: 2 threads per row, 16 units each
    const int row_l = tid >> 1;
    const int half = tid & 1;
    const int row = m0 + row_l;
    const int t = row & (Ss - 1), bidx = row >> 10;
    const int tp = dir ? (t + WSw - step) : (t - WSw + step);
    const bool valid = ((unsigned)tp < (unsigned)Ss);
    const int tok = valid ? x[(bidx << 10) + tp] : 0;
    const bool finalstep = (step == WSw);

    const float4* accu = (const float4*)(Acc + row_l * 128 + (half << 6));
    const float4* bsu  = (const float4*)(biasf + (half << 6));
    const float4* pvu  = (const float4*)(g_PVp[dir] + (size_t)tok * G4H + (nblk << 7) + (half << 6));
    float4* cp = (float4*)(g_cst[dir] + (size_t)row * Hh + (nblk << 5) + (half << 4));
    const int colbase = (nblk << 5) + (half << 4);
    __half* hip = g_hA[dir][nbuf] + (size_t)row * Hh + colbase;
    __half* fHp = g_fcA + (size_t)row * FHh + dir * Hh + colbase;

    uint32_t hwH[8], fwH[8];
#pragma unroll
    for (int g4 = 0; g4 < 4; g4++) {
        float4 cv = cp[g4];
        float cin[4] = {cv.x, cv.y, cv.z, cv.w};
        float ho[4];
#pragma unroll
        for (int j = 0; j < 4; j++) {
            int u = g4 * 4 + j;
            float4 gq = accu[u];
            float4 bq = bsu[u];
            float pi = gq.x + bq.x, pf = gq.y + bq.y, pg = gq.z + bq.z, po = gq.w + bq.w;
            if (valid) {
                float4 pq = pvu[u];
                pi += pq.x; pf += pq.y; pg += pq.z; po += pq.w;
            }
            float iv = sigmoidf_(pi), fv = sigmoidf_(pf), gv = tanhf(pg), ov = sigmoidf_(po);
            float cn = fv * cin[j] + iv * gv;
            cin[j] = cn;
            ho[j] = ov * tanhf(cn);
        }
        cp[g4] = make_float4(cin[0], cin[1], cin[2], cin[3]);
        hwH[g4 * 2 + 0] = packh(__float2half(ho[0]), __float2half(ho[1]));
        hwH[g4 * 2 + 1] = packh(__float2half(ho[2]), __float2half(ho[3]));
        if (finalstep) {
            fwH[g4 * 2 + 0] = packh(__float2half(leakyf_(ho[0])), __float2half(leakyf_(ho[1])));
            fwH[g4 * 2 + 1] = packh(__float2half(leakyf_(ho[2])), __float2half(leakyf_(ho[3])));
        }
    }
    *(uint4*)hip       = make_uint4(hwH[0], hwH[1], hwH[2], hwH[3]);
    *(uint4*)(hip + 8) = make_uint4(hwH[4], hwH[5], hwH[6], hwH[7]);
    if (finalstep) {
        *(uint4*)fHp       = make_uint4(fwH[0], fwH[1], fwH[2], fwH[3]);
        *(uint4*)(fHp + 8) = make_uint4(fwH[4], fwH[5], fwH[6], fwH[7]);
    }
}

// ---------------------------------------------------------------------------
// fc1_mma: g_fc1 = leaky( fcA @ fc1_w^T + fc1_b ). fp16 1-term, 2 CTAs/SM.
// grid (4 nblk, 128 mtile), 256 thr. K=512 in 8 chunks.
// ---------------------------------------------------------------------------
__global__ void __launch_bounds__(256, 2) fc1_mma(const float* __restrict__ fc1_b)
{
    extern __shared__ unsigned char smraw[];
    uint32_t sb0 = smem_u32(smraw);
    uint32_t sb = (sb0 + 1023u) & ~1023u;
    unsigned char* smb = smraw + (sb - sb0);

    const int nblk = blockIdx.x;
    const int m0 = blockIdx.y << 7;
    const int tid = threadIdx.x;
    const int lane = tid & 31, wid = tid >> 5;
    const int wm = wid >> 2, wn = wid & 3;

    float* biasf = (float*)(smb + 65536);
    if (tid < 32)
        *(float4*)(biasf + (tid << 2)) = *(const float4*)(fc1_b + (nblk << 7) + (tid << 2));

    float acc[4][4][4];
#pragma unroll
    for (int a = 0; a < 4; a++)
#pragma unroll
        for (int b = 0; b < 4; b++)
#pragma unroll
            for (int c = 0; c < 4; c++) acc[a][b][c] = 0.f;

    const int arow = (wm << 6) + (lane & 15);
    const int atop = (lane >> 4) << 4;
    const int brow = (wn << 5) + (lane & 7) + ((lane & 16) ? 8 : 0);
    const int btop = (lane & 8) ? 16 : 0;

    for (int kc = 0; kc < 8; kc++) {
        const uint4* srcA = (const uint4*)g_fcA;
#pragma unroll
        for (int i = 0; i < 4; i++) {
            int u = tid + (i << 8);
            int r = u >> 3, c16 = u & 7;
            uint32_t dst = sb + swz128((uint32_t)r * 128u + ((uint32_t)c16 << 4));
            cpasync16(dst, &srcA[(size_t)(m0 + r) * 64 + (kc << 3) + c16]);
        }
        {
            const unsigned char* src = &g_fc1Bsw[nblk][kc][0];
#pragma unroll
            for (int i = 0; i < 4; i++) {
                uint32_t o = ((uint32_t)tid + ((uint32_t)i << 8)) << 4;
                cpasync16(sb + 16384u + o, src + o);
            }
        }
        CPASYNC_COMMIT();
        CPASYNC_WAIT_ALL();
        __syncthreads();

        const uint32_t aB = sb, bB = sb + 16384u;
#pragma unroll
        for (int ks = 0; ks < 4; ks++) {
            const uint32_t kbyte = (uint32_t)ks << 5;
            uint32_t ah[4][4], bh[8];
#pragma unroll
            for (int mi = 0; mi < 4; mi++) {
                uint32_t off = swz128((uint32_t)(arow + mi * 16) * 128u + kbyte + (uint32_t)atop);
                ldsm4(ah[mi], aB + off);
            }
#pragma unroll
            for (int bi = 0; bi < 2; bi++) {
                uint32_t off = swz128((uint32_t)(brow + bi * 16) * 128u + kbyte + (uint32_t)btop);
                ldsm4(bh + bi * 4, bB + off);
            }
#pragma unroll
            for (int mi = 0; mi < 4; mi++)
#pragma unroll
                for (int ni = 0; ni < 4; ni++)
                    mma_f16(acc[mi][ni], ah[mi], bh + ni * 2);
        }
        __syncthreads();
    }

    // epilogue: bias + leaky, direct register store
#pragma unroll
    for (int mi = 0; mi < 4; mi++) {
        int r0 = m0 + (wm << 6) + mi * 16 + (lane >> 2);
#pragma unroll
        for (int ni = 0; ni < 4; ni++) {
            int cl = (wn << 5) + ni * 8 + ((lane & 3) << 1);
            int c0 = (nblk << 7) + cl;
            float b0 = biasf[cl], b1 = biasf[cl + 1];
            *(float2*)(g_fc1 + (size_t)r0 * FHh + c0) =
                make_float2(leakyf_(acc[mi][ni][0] + b0), leakyf_(acc[mi][ni][1] + b1));
            *(float2*)(g_fc1 + (size_t)(r0 + 8) * FHh + c0) =
                make_float2(leakyf_(acc[mi][ni][2] + b0), leakyf_(acc[mi][ni][3] + b1));
        }
    }
}

// ---------------------------------------------------------------------------
// fc2: out[n] = sigmoid( g_fc1[n] . fc2_w + fc2_b )
// ---------------------------------------------------------------------------
__global__ void __launch_bounds__(128) fc2_kernel(const float* __restrict__ w,
                                                  const float* __restrict__ b,
                                                  float* __restrict__ out)
{
    const int n = blockIdx.x;
    const int t = threadIdx.x;
    const float4 a = ((const float4*)(g_fc1 + (size_t)n * FHh))[t];
    const float4 wv = ((const float4*)w)[t];
    float s = a.x * wv.x + a.y * wv.y + a.z * wv.z + a.w * wv.w;
#pragma unroll
    for (int o = 16; o > 0; o >>= 1) s += __shfl_xor_sync(0xffffffffu, s, o);
    __shared__ float ws[4];
    if ((t & 31) == 0) ws[t >> 5] = s;
    __syncthreads();
    if (t == 0) {
        const float tot = ws[0] + ws[1] + ws[2] + ws[3];
        out[n] = 1.0f / (1.0f + expf(-(tot + b[0])));
    }
}

// ---------------------------------------------------------------------------
extern "C" void kernel_launch(void* const* d_in, const int* in_sizes, int n_in,
                              void* d_out, int out_size)
{
    const int*   x      = (const int*)  d_in[0];
    const float* embed  = (const float*)d_in[1];
    const float* Wih_f  = (const float*)d_in[2];
    const float* Whh_f  = (const float*)d_in[3];
    const float* bih_f  = (const float*)d_in[4];
    const float* bhh_f  = (const float*)d_in[5];
    const float* Wih_b  = (const float*)d_in[6];
    const float* Whh_b  = (const float*)d_in[7];
    const float* bih_b  = (const float*)d_in[8];
    const float* bhh_b  = (const float*)d_in[9];
    const float* fc1_w  = (const float*)d_in[10];
    const float* fc1_b  = (const float*)d_in[11];
    const float* fc2_w  = (const float*)d_in[12];
    const float* fc2_b  = (const float*)d_in[13];
    float* out = (float*)d_out;

    cudaFuncSetAttribute(gates_mma, cudaFuncAttributeMaxDynamicSharedMemorySize, SB_SMEM);
    cudaFuncSetAttribute(fc1_mma,   cudaFuncAttributeMaxDynamicSharedMemorySize, SB_SMEM);
    cudaFuncSetAttribute(pv_mma,    cudaFuncAttributeMaxDynamicSharedMemorySize, PV_SMEM);

    prep_all<<<640, 256>>>(Whh_f, Whh_b, Wih_f, Wih_b, fc1_w,
                           bih_f, bhh_f, bih_b, bhh_b);
    pv_mma<<<dim3(8, 63, 2), 256, PV_SMEM>>>(embed);

    // step 0 (h0 = 0): exact elementwise init, no GEMM
    gates_init<<<4096, 256>>>(x);

    for (int k = 1; k <= WSw; k++) {
        gates_mma<<<dim3(8, NTOK / 128, 2), 256, SB_SMEM>>>(x, k);
    }

    fc1_mma<<<dim3(4, 128), 256, SB_SMEM>>>(fc1_b);
    fc2_kernel<<<NTOK, 128>>>(fc2_w, fc2_b, out);
}